// round 4
// baseline (speedup 1.0000x reference)
#include <cuda_runtime.h>
#include <math.h>

#define NB 8
#define NC 64
#define NG 4
#define CG 16
#define NH 128
#define NW 128
#define HW (NH*NW)
#define IMG (NB*NC*HW)
#define NROW (NB*NH)

typedef unsigned long long u64;

__device__ __forceinline__ u64 f2dup(float v) {
  u64 r; asm("mov.b64 %0, {%1, %1};" : "=l"(r) : "f"(v)); return r;
}
__device__ __forceinline__ u64 f2pk(float a, float b) {
  u64 r; asm("mov.b64 %0, {%1, %2};" : "=l"(r) : "f"(a), "f"(b)); return r;
}
__device__ __forceinline__ void fma2(u64& d, u64 a, u64 b) {
  asm("fma.rn.f32x2 %0, %1, %2, %0;" : "+l"(d) : "l"(a), "l"(b));
}
__device__ __forceinline__ float2 f2up(u64 v) {
  float2 f; asm("mov.b64 {%0, %1}, %2;" : "=f"(f.x), "=f"(f.y) : "l"(v)); return f;
}

// ---------------- scratch ----------------------------------------------------
__device__ float g_t1[2*(size_t)IMG];
__device__ float g_t2[2*(size_t)IMG];
__device__ float g_bnA[2][NC];
__device__ float g_bnB[2][NC];

// ---------------- BN statistics ----------------------------------------------
__global__ __launch_bounds__(256) void bn_stats_kernel(
    const float* __restrict__ xl, const float* __restrict__ xr,
    const float* __restrict__ gamma, const float* __restrict__ beta) {
  int c = blockIdx.x & 63;
  int img = blockIdx.x >> 6;
  const float4* x = (const float4*)(img ? xr : xl);
  int t = threadIdx.x;
  float s = 0.f, s2 = 0.f;
  for (int b = 0; b < NB; b++) {
    const float4* p = x + (size_t)(b*NC + c)*(HW/4);
    for (int i = t; i < HW/4; i += 256) {
      float4 v = p[i];
      s  += v.x + v.y + v.z + v.w;
      s2 += v.x*v.x + v.y*v.y + v.z*v.z + v.w*v.w;
    }
  }
  __shared__ float sh[256], sh2[256];
  sh[t] = s; sh2[t] = s2; __syncthreads();
  for (int off = 128; off; off >>= 1) {
    if (t < off) { sh[t] += sh[t+off]; sh2[t] += sh2[t+off]; }
    __syncthreads();
  }
  if (t == 0) {
    const float inv = 1.f / (float)(NB*HW);
    float mean = sh[0] * inv;
    float var  = sh2[0] * inv - mean*mean;
    float a = gamma[c] * rsqrtf(var + 1e-5f);
    g_bnA[img][c] = a;
    g_bnB[img][c] = beta[c] - mean * a;
  }
}

// ---------------- grouped 3x3 conv: 8oc x 4w per thread ----------------------
#define IN_ST 132
#define CONV_SMEM ((CG*6*IN_ST + CG*CG*9)*4)

template<bool FIRST>
__global__ __launch_bounds__(256, 3) void conv3x3_kernel(
    const float* __restrict__ xL, const float* __restrict__ xR,
    float* __restrict__ t1, float* __restrict__ t2,
    const float* __restrict__ wgt, const float* __restrict__ bias) {
  extern __shared__ float sm[];
  float* in_s = sm;                 // [16ic][6r][132]
  float* w_s  = sm + CG*6*IN_ST;    // [ic][kh][kw][16oc]
  int t = threadIdx.x;
  int img = blockIdx.z;
  int b = blockIdx.y >> 2, g = blockIdx.y & 3;
  int h0 = blockIdx.x * 4;
  const float* xorig = img ? xR : xL;
  const float* xin = FIRST ? xorig : (t1 + (size_t)img*IMG);
  float* out = (FIRST ? t1 : t2) + (size_t)img*IMG;

  for (int i = t; i < CG*CG*9; i += 256) {
    int oc = i / 144, r = i - oc*144;
    w_s[r*16 + oc] = wgt[g*CG*CG*9 + i];
  }
  for (int i = t; i < CG*6*IN_ST; i += 256) {
    int ic  = i / (6*IN_ST);
    int rem = i - ic*(6*IN_ST);
    int r   = rem / IN_ST;
    int wc  = rem - r*IN_ST;
    int hh  = h0 - 1 + r;
    int ww  = wc - 1;
    float v = 0.f;
    if ((unsigned)hh < (unsigned)NH && (unsigned)ww < (unsigned)NW) {
      v = xin[((size_t)(b*NC + g*CG + ic)*NH + hh)*NW + ww];
      if (FIRST) v = g_bnA[img][g*CG+ic]*v + g_bnB[img][g*CG+ic];
    }
    in_s[i] = v;
  }
  __syncthreads();

  int wseg = t & 31, hh2 = (t >> 5) & 3, ocq = t >> 7;
  int w0 = wseg * 4, oc0 = ocq * 8;

  // acc2[p][j]: oc pair p (oc0+2p, oc0+2p+1), output column w0+j
  u64 acc2[4][4];
  #pragma unroll
  for (int p = 0; p < 4; p++) {
    u64 bz = f2pk(bias[g*CG+oc0+2*p], bias[g*CG+oc0+2*p+1]);
    #pragma unroll
    for (int j = 0; j < 4; j++) acc2[p][j] = bz;
  }

  for (int ic = 0; ic < CG; ic++) {
    #pragma unroll
    for (int kh = 0; kh < 3; kh++) {
      const float* row = in_s + (ic*6 + hh2 + kh)*IN_ST + w0;
      float4 A  = *(const float4*)row;
      float2 C2 = *(const float2*)(row + 4);
      u64 ind[6];
      ind[0]=f2dup(A.x); ind[1]=f2dup(A.y); ind[2]=f2dup(A.z);
      ind[3]=f2dup(A.w); ind[4]=f2dup(C2.x); ind[5]=f2dup(C2.y);
      #pragma unroll
      for (int kw = 0; kw < 3; kw++) {
        const float* wb = &w_s[((ic*3+kh)*3 + kw)*16 + oc0];
        ulonglong2 wA = *(const ulonglong2*)wb;
        ulonglong2 wB = *(const ulonglong2*)(wb + 4);
        #pragma unroll
        for (int j = 0; j < 4; j++) {
          fma2(acc2[0][j], ind[kw+j], wA.x);
          fma2(acc2[1][j], ind[kw+j], wA.y);
          fma2(acc2[2][j], ind[kw+j], wB.x);
          fma2(acc2[3][j], ind[kw+j], wB.y);
        }
      }
    }
  }

  int hout = h0 + hh2;
  #pragma unroll
  for (int o = 0; o < 8; o++) {
    int ch = g*CG + oc0 + o;
    size_t idx = ((size_t)(b*NC + ch)*NH + hout)*NW + w0;
    float r[4];
    #pragma unroll
    for (int j = 0; j < 4; j++) {
      float2 f = f2up(acc2[o>>1][j]);
      r[j] = (o & 1) ? f.y : f.x;
    }
    if (FIRST) {
      #pragma unroll
      for (int j = 0; j < 4; j++) r[j] = r[j] > 0.f ? r[j] : 0.1f*r[j];
    } else {
      float ra = g_bnA[img][ch], rb = g_bnB[img][ch];
      float4 x0 = *(const float4*)&xorig[idx];
      float xs[4] = {x0.x,x0.y,x0.z,x0.w};
      #pragma unroll
      for (int j = 0; j < 4; j++) r[j] = r[j] + ra*xs[j] + rb;
    }
    *(float4*)&out[idx] = make_float4(r[0],r[1],r[2],r[3]);
  }
}

// ---------------- fused attention ---------------------------------------------
#define ST 128
#define XST 68
#define OFF_BM    16384
#define OFF_XLS   32768
#define OFF_XRS   41472
#define OFF_WS    50176
#define OFF_BS    52224
#define OFF_RMAX  52352
#define OFF_RSUMI 52480
#define OFF_CMAX  52608
#define OFF_CSUMI 52736
#define OFF_VL    52864
#define OFF_VR    52992
#define OFF_PART  53120
#define OFF_FR    55168
#define OFF_GC    55296
#define OFF_MG    55424
#define ATTN_SMEM ((55424 + 32)*4)

__global__ __launch_bounds__(512, 1) void attn_kernel(
    const float* __restrict__ t2, const float* __restrict__ xL,
    const float* __restrict__ xR,
    const float* __restrict__ qw, const float* __restrict__ qb,
    const float* __restrict__ kw_, const float* __restrict__ kb,
    float* __restrict__ outL, float* __restrict__ outR) {
  extern __shared__ float sm[];
  float* Am    = sm;               // t2 stage -> S -> E_rl (row-major)
  float* Bm    = sm + OFF_BM;      // Q/K (k-major) -> E_lr^T
  float* xls   = sm + OFF_XLS;     // [v][c] stride 68
  float* xrs   = sm + OFF_XRS;
  float* ws    = sm + OFF_WS;
  float* bs    = sm + OFF_BS;
  float* rmax  = sm + OFF_RMAX;
  float* rsumI = sm + OFF_RSUMI;
  float* cmax  = sm + OFF_CMAX;
  float* csumI = sm + OFF_CSUMI;
  float* Vl    = sm + OFF_VL;
  float* Vr    = sm + OFF_VR;
  float* part  = sm + OFF_PART;    // 2048
  float* fr    = sm + OFF_FR;
  float* gc    = sm + OFF_GC;
  float* Mg    = sm + OFF_MG;
  int n = blockIdx.x, b = n >> 7, h = n & 127;
  int t = threadIdx.x, warp = t >> 5, lane = t & 31;

  // stage weights/bias + both t2 rows
  for (int i = t; i < 2048; i += 512) ws[i] = (i < 1024) ? qw[i] : kw_[i-1024];
  if (t < 128) bs[t] = (t < 64) ? qb[t] : kb[t-64];
  for (int i = t; i < 16384; i += 512) {
    int c = i >> 7, u = i & 127;
    size_t gi = ((c >= 64) ? (size_t)IMG : 0) +
                ((size_t)(b*NC + (c & 63))*NH + h)*NW + u;
    Am[c*ST + u] = t2[gi];
  }
  __syncthreads();

  // 1x1 grouped conv (f32x2, pairs over u): Bm[k][u]
  for (int i = t; i < 8192; i += 512) {
    int k = i >> 6, up = (i & 63)*2;
    int cb = (k >> 4) * 16;
    float bzv = bs[k];
    u64 a = f2pk(bzv, bzv);
    #pragma unroll
    for (int ic = 0; ic < 16; ic++) {
      u64 w2 = f2dup(ws[k*16 + ic]);
      u64 xp = *(const u64*)&Am[(cb + ic)*ST + up];
      fma2(a, w2, xp);
    }
    *(u64*)&Bm[k*ST + up] = a;
  }
  __syncthreads();

  // row-mean subtract
  for (int r = warp; r < 128; r += 16) {
    float s = 0.f;
    for (int u = lane; u < 128; u += 32) s += Bm[r*ST + u];
    #pragma unroll
    for (int off = 16; off; off >>= 1) s += __shfl_xor_sync(0xffffffffu, s, off);
    float mean = s * (1.f/128.f);
    for (int u = lane; u < 128; u += 32) Bm[r*ST + u] -= mean;
  }
  __syncthreads();

  // GEMM1: S[u][v] = sum_k Q[k][u]*K[k][v]   (4u x 8v per thread)
  {
    int u0 = (t >> 4) * 4, v0 = (t & 15) * 8;
    u64 acc2[4][4];
    #pragma unroll
    for (int i = 0; i < 4; i++)
      #pragma unroll
      for (int p = 0; p < 4; p++) acc2[i][p] = 0ull;
    for (int k = 0; k < 64; k++) {
      float4 qv = *(const float4*)&Bm[k*ST + u0];
      ulonglong2 ka = *(const ulonglong2*)&Bm[(64+k)*ST + v0];
      ulonglong2 kb2 = *(const ulonglong2*)&Bm[(64+k)*ST + v0 + 4];
      u64 q0 = f2dup(qv.x), q1 = f2dup(qv.y), q2 = f2dup(qv.z), q3 = f2dup(qv.w);
      fma2(acc2[0][0], q0, ka.x); fma2(acc2[0][1], q0, ka.y);
      fma2(acc2[0][2], q0, kb2.x); fma2(acc2[0][3], q0, kb2.y);
      fma2(acc2[1][0], q1, ka.x); fma2(acc2[1][1], q1, ka.y);
      fma2(acc2[1][2], q1, kb2.x); fma2(acc2[1][3], q1, kb2.y);
      fma2(acc2[2][0], q2, ka.x); fma2(acc2[2][1], q2, ka.y);
      fma2(acc2[2][2], q2, kb2.x); fma2(acc2[2][3], q2, kb2.y);
      fma2(acc2[3][0], q3, ka.x); fma2(acc2[3][1], q3, ka.y);
      fma2(acc2[3][2], q3, kb2.x); fma2(acc2[3][3], q3, kb2.y);
    }
    #pragma unroll
    for (int i = 0; i < 4; i++) {
      float2 a = f2up(acc2[i][0]), c2 = f2up(acc2[i][1]);
      float2 d = f2up(acc2[i][2]), e2 = f2up(acc2[i][3]);
      *(float4*)&Am[(u0+i)*ST + v0]     = make_float4(a.x,a.y,c2.x,c2.y);
      *(float4*)&Am[(u0+i)*ST + v0 + 4] = make_float4(d.x,d.y,e2.x,e2.y);
    }
  }
  __syncthreads();

  // Phase A: maxes + x staging (warp-specialized)
  if (warp < 8) {                     // row maxes
    for (int r = warp*16; r < warp*16 + 16; r++) {
      float m = -1e30f;
      for (int j = lane; j < 128; j += 32) m = fmaxf(m, Am[r*ST + j]);
      #pragma unroll
      for (int off = 16; off; off >>= 1) m = fmaxf(m, __shfl_xor_sync(0xffffffffu, m, off));
      if (lane == 0) rmax[r] = m;
    }
  } else if (warp < 12) {             // column maxes
    int col = (warp - 8)*32 + lane;
    float m0=-1e30f, m1=-1e30f, m2=-1e30f, m3=-1e30f;
    for (int r = 0; r < 128; r += 4) {
      m0 = fmaxf(m0, Am[(r+0)*ST + col]);
      m1 = fmaxf(m1, Am[(r+1)*ST + col]);
      m2 = fmaxf(m2, Am[(r+2)*ST + col]);
      m3 = fmaxf(m3, Am[(r+3)*ST + col]);
    }
    cmax[col] = fmaxf(fmaxf(m0,m1), fmaxf(m2,m3));
  } else {                            // stage x rows [v][c]
    for (int i = t - 384; i < 8192; i += 128) {
      int c = i >> 7, v = i & 127;
      size_t gi = ((size_t)(b*NC + c)*NH + h)*NW + v;
      xls[v*XST + c] = xL[gi];
      xrs[v*XST + c] = xR[gi];
    }
  }
  __syncthreads();

  // global max + rank-1 softmax factors
  if (t < 32) {
    float m = fmaxf(fmaxf(rmax[t], rmax[t+32]), fmaxf(rmax[t+64], rmax[t+96]));
    #pragma unroll
    for (int off = 16; off; off >>= 1) m = fmaxf(m, __shfl_xor_sync(0xffffffffu, m, off));
    if (t == 0) Mg[0] = m;
  }
  __syncthreads();
  if (t < 128) {
    float M = Mg[0];
    fr[t] = __expf(rmax[t] - M);    // <= 1
    gc[t] = __expf(M - cmax[t]);    // >= 1
  }
  __syncthreads();

  // Phase B: one exp per element; E_lr derived by rank-1 multiply
  {
    float gcv[4];
    #pragma unroll
    for (int k = 0; k < 4; k++) gcv[k] = gc[lane + k*32];
    float csump[4] = {0.f, 0.f, 0.f, 0.f};
    for (int rr = 0; rr < 8; rr++) {
      int r = warp*8 + rr;
      float rm = rmax[r];
      float frv = fr[r];
      float rs = 0.f;
      #pragma unroll
      for (int k = 0; k < 4; k++) {
        int c = lane + k*32;
        float e = __expf(Am[r*ST + c] - rm);
        Am[r*ST + c] = e;
        float el = e * (frv * gcv[k]);
        Bm[r*ST + c] = el;
        rs += e;
        csump[k] += el;
      }
      #pragma unroll
      for (int off = 16; off; off >>= 1) rs += __shfl_xor_sync(0xffffffffu, rs, off);
      if (lane == 0) rsumI[r] = 1.f / rs;
    }
    #pragma unroll
    for (int k = 0; k < 4; k++) part[warp*128 + k*32 + lane] = csump[k];
  }
  __syncthreads();
  if (t < 128) {
    float s = 0.f;
    #pragma unroll
    for (int w = 0; w < 16; w++) s += part[w*128 + t];
    csumI[t] = 1.f / s;
  }
  __syncthreads();

  // V_left[u] = sum_v (sum_d rsumI[u+d]*E_rl[u+d][v]) * E_lr^T[u][v]*csumI[v]
  for (int u = warp; u < 128; u += 16) {
    float rI[5];
    #pragma unroll
    for (int d = 0; d < 5; d++) {
      int ui = u + d - 2;
      rI[d] = ((unsigned)ui < 128u) ? rsumI[ui] : 0.f;
    }
    float acc = 0.f;
    for (int v = lane; v < 128; v += 32) {
      float s5 = 0.f;
      #pragma unroll
      for (int d = 0; d < 5; d++) {
        int ui = u + d - 2;
        if ((unsigned)ui < 128u) s5 += rI[d]*Am[ui*ST + v];
      }
      acc += s5 * Bm[u*ST + v] * csumI[v];
    }
    #pragma unroll
    for (int off = 16; off; off >>= 1) acc += __shfl_xor_sync(0xffffffffu, acc, off);
    if (lane == 0) Vl[u] = tanhf(5.f*acc);
  }
  // V_right[u] = sum_v E_rl[v][u]*rsumI[v] * (sum_d E_lr^T[v][u+d]*csumI[u+d])
  {
    int u = (warp & 3)*32 + lane;
    int v0 = (warp >> 2)*32;
    float ci[5];
    #pragma unroll
    for (int d = 0; d < 5; d++) {
      int ui = u + d - 2;
      ci[d] = ((unsigned)ui < 128u) ? csumI[ui] : 0.f;
    }
    float acc = 0.f;
    for (int v = v0; v < v0 + 32; v++) {
      float s5 = 0.f;
      #pragma unroll
      for (int d = 0; d < 5; d++) {
        int ui = u + d - 2;
        if ((unsigned)ui < 128u) s5 += Bm[v*ST + ui]*ci[d];
      }
      acc += Am[v*ST + u] * rsumI[v] * s5;
    }
    part[(warp >> 2)*128 + u] = acc;
  }
  __syncthreads();
  if (t < 128) Vr[t] = tanhf(5.f*(part[t] + part[128+t] + part[256+t] + part[384+t]));

  // GEMM2 (g0): xlT[u][c] = rsumI[u]*sum_v E_rl[u][v]*xr[v][c]   (4u x 8c)
  // GEMM3 (g1): xrT[u][c] = csumI[u]*sum_v E_lr^T[v][u]*xl[v][c] (4u x 8c)
  int group = t >> 8;
  int tid = t & 255;
  int c0 = (tid & 7)*8, u0 = (tid >> 3)*4;
  u64 acc2[4][4];
  #pragma unroll
  for (int i = 0; i < 4; i++)
    #pragma unroll
    for (int p = 0; p < 4; p++) acc2[i][p] = 0ull;

  if (group == 0) {
    for (int v0g = 0; v0g < 128; v0g += 4) {
      ulonglong2 xv[4][2];
      #pragma unroll
      for (int vv = 0; vv < 4; vv++) {
        xv[vv][0] = *(const ulonglong2*)&xrs[(v0g+vv)*XST + c0];
        xv[vv][1] = *(const ulonglong2*)&xrs[(v0g+vv)*XST + c0 + 4];
      }
      #pragma unroll
      for (int i = 0; i < 4; i++) {
        float4 m = *(const float4*)&Am[(u0+i)*ST + v0g];
        u64 m0 = f2dup(m.x), m1 = f2dup(m.y), m2 = f2dup(m.z), m3 = f2dup(m.w);
        fma2(acc2[i][0], m0, xv[0][0].x); fma2(acc2[i][1], m0, xv[0][0].y);
        fma2(acc2[i][2], m0, xv[0][1].x); fma2(acc2[i][3], m0, xv[0][1].y);
        fma2(acc2[i][0], m1, xv[1][0].x); fma2(acc2[i][1], m1, xv[1][0].y);
        fma2(acc2[i][2], m1, xv[1][1].x); fma2(acc2[i][3], m1, xv[1][1].y);
        fma2(acc2[i][0], m2, xv[2][0].x); fma2(acc2[i][1], m2, xv[2][0].y);
        fma2(acc2[i][2], m2, xv[2][1].x); fma2(acc2[i][3], m2, xv[2][1].y);
        fma2(acc2[i][0], m3, xv[3][0].x); fma2(acc2[i][1], m3, xv[3][0].y);
        fma2(acc2[i][2], m3, xv[3][1].x); fma2(acc2[i][3], m3, xv[3][1].y);
      }
    }
  } else {
    for (int v0g = 0; v0g < 128; v0g += 4) {
      #pragma unroll
      for (int vv = 0; vv < 4; vv++) {
        int v = v0g + vv;
        ulonglong2 xa = *(const ulonglong2*)&xls[v*XST + c0];
        ulonglong2 xb = *(const ulonglong2*)&xls[v*XST + c0 + 4];
        float4 m = *(const float4*)&Bm[v*ST + u0];
        u64 m0 = f2dup(m.x), m1 = f2dup(m.y), m2 = f2dup(m.z), m3 = f2dup(m.w);
        fma2(acc2[0][0], m0, xa.x); fma2(acc2[0][1], m0, xa.y);
        fma2(acc2[0][2], m0, xb.x); fma2(acc2[0][3], m0, xb.y);
        fma2(acc2[1][0], m1, xa.x); fma2(acc2[1][1], m1, xa.y);
        fma2(acc2[1][2], m1, xb.x); fma2(acc2[1][3], m1, xb.y);
        fma2(acc2[2][0], m2, xa.x); fma2(acc2[2][1], m2, xa.y);
        fma2(acc2[2][2], m2, xb.x); fma2(acc2[2][3], m2, xb.y);
        fma2(acc2[3][0], m3, xa.x); fma2(acc2[3][1], m3, xa.y);
        fma2(acc2[3][2], m3, xb.x); fma2(acc2[3][3], m3, xb.y);
      }
    }
  }
  __syncthreads();

  // blend in place (normalization folded)
  if (group == 0) {
    #pragma unroll
    for (int i = 0; i < 4; i++) {
      int u = u0 + i;
      float vl = Vl[u];
      float gsc = vl * rsumI[u];
      float xt[8];
      #pragma unroll
      for (int p = 0; p < 4; p++) {
        float2 f = f2up(acc2[i][p]);
        xt[2*p] = f.x; xt[2*p+1] = f.y;
      }
      #pragma unroll
      for (int cc = 0; cc < 8; cc++) {
        int x = u*XST + c0 + cc;
        xls[x] = xls[x]*(1.f - vl) + xt[cc]*gsc;
      }
    }
  } else {
    #pragma unroll
    for (int i = 0; i < 4; i++) {
      int u = u0 + i;
      float vr = Vr[u];
      float gsc = vr * csumI[u];
      float xt[8];
      #pragma unroll
      for (int p = 0; p < 4; p++) {
        float2 f = f2up(acc2[i][p]);
        xt[2*p] = f.x; xt[2*p+1] = f.y;
      }
      #pragma unroll
      for (int cc = 0; cc < 8; cc++) {
        int x = u*XST + c0 + cc;
        xrs[x] = xrs[x]*(1.f - vr) + xt[cc]*gsc;
      }
    }
  }
  __syncthreads();

  for (int i = t; i < 8192; i += 512) {
    int c = i >> 7, u = i & 127;
    size_t gi = ((size_t)(b*NC + c)*NH + h)*NW + u;
    outL[gi] = xls[u*XST + c];
    outR[gi] = xrs[u*XST + c];
  }
}

// ---------------- host ------------------------------------------------------
extern "C" void kernel_launch(void* const* d_in, const int* in_sizes, int n_in,
                              void* d_out, int out_size) {
  const float* xL    = (const float*)d_in[0];
  const float* xR    = (const float*)d_in[1];
  const float* gamma = (const float*)d_in[2];
  const float* beta  = (const float*)d_in[3];
  const float* w1    = (const float*)d_in[4];
  const float* b1    = (const float*)d_in[5];
  const float* w2    = (const float*)d_in[6];
  const float* b2    = (const float*)d_in[7];
  const float* qw    = (const float*)d_in[8];
  const float* qb    = (const float*)d_in[9];
  const float* kw    = (const float*)d_in[10];
  const float* kb    = (const float*)d_in[11];
  float* outL = (float*)d_out;
  float* outR = outL + (size_t)IMG;

  float *t1, *t2;
  cudaGetSymbolAddress((void**)&t1, g_t1);
  cudaGetSymbolAddress((void**)&t2, g_t2);

  cudaFuncSetAttribute(conv3x3_kernel<true>,  cudaFuncAttributeMaxDynamicSharedMemorySize, CONV_SMEM);
  cudaFuncSetAttribute(conv3x3_kernel<false>, cudaFuncAttributeMaxDynamicSharedMemorySize, CONV_SMEM);
  cudaFuncSetAttribute(attn_kernel, cudaFuncAttributeMaxDynamicSharedMemorySize, ATTN_SMEM);

  bn_stats_kernel<<<128, 256>>>(xL, xR, gamma, beta);

  dim3 cgrid(NH/4, NB*NG, 2);
  conv3x3_kernel<true ><<<cgrid, 256, CONV_SMEM>>>(xL, xR, t1, t2, w1, b1);
  conv3x3_kernel<false><<<cgrid, 256, CONV_SMEM>>>(xL, xR, t1, t2, w2, b2);

  attn_kernel<<<NROW, 512, ATTN_SMEM>>>(t2, xL, xR, qw, qb, kw, kb, outL, outR);
}

// round 5
// speedup vs baseline: 1.1334x; 1.1334x over previous
#include <cuda_runtime.h>
#include <math.h>

#define NB 8
#define NC 64
#define NG 4
#define CG 16
#define NH 128
#define NW 128
#define HW (NH*NW)
#define IMG (NB*NC*HW)
#define NROW (NB*NH)

typedef unsigned long long u64;

__device__ __forceinline__ u64 f2dup(float v) {
  u64 r; asm("mov.b64 %0, {%1, %1};" : "=l"(r) : "f"(v)); return r;
}
__device__ __forceinline__ u64 f2pk(float a, float b) {
  u64 r; asm("mov.b64 %0, {%1, %2};" : "=l"(r) : "f"(a), "f"(b)); return r;
}
__device__ __forceinline__ void fma2(u64& d, u64 a, u64 b) {
  asm("fma.rn.f32x2 %0, %1, %2, %0;" : "+l"(d) : "l"(a), "l"(b));
}
__device__ __forceinline__ float2 f2up(u64 v) {
  float2 f; asm("mov.b64 {%0, %1}, %2;" : "=f"(f.x), "=f"(f.y) : "l"(v)); return f;
}

// ---------------- scratch ----------------------------------------------------
__device__ float g_t1[2*(size_t)IMG];
__device__ float g_t2[2*(size_t)IMG];
__device__ float g_bnA[2][NC];
__device__ float g_bnB[2][NC];

// ---------------- BN statistics ----------------------------------------------
__global__ __launch_bounds__(256) void bn_stats_kernel(
    const float* __restrict__ xl, const float* __restrict__ xr,
    const float* __restrict__ gamma, const float* __restrict__ beta) {
  int c = blockIdx.x & 63;
  int img = blockIdx.x >> 6;
  const float4* x = (const float4*)(img ? xr : xl);
  int t = threadIdx.x;
  float s = 0.f, s2 = 0.f;
  for (int b = 0; b < NB; b++) {
    const float4* p = x + (size_t)(b*NC + c)*(HW/4);
    for (int i = t; i < HW/4; i += 256) {
      float4 v = p[i];
      s  += v.x + v.y + v.z + v.w;
      s2 += v.x*v.x + v.y*v.y + v.z*v.z + v.w*v.w;
    }
  }
  __shared__ float sh[256], sh2[256];
  sh[t] = s; sh2[t] = s2; __syncthreads();
  for (int off = 128; off; off >>= 1) {
    if (t < off) { sh[t] += sh[t+off]; sh2[t] += sh2[t+off]; }
    __syncthreads();
  }
  if (t == 0) {
    const float inv = 1.f / (float)(NB*HW);
    float mean = sh[0] * inv;
    float var  = sh2[0] * inv - mean*mean;
    float a = gamma[c] * rsqrtf(var + 1e-5f);
    g_bnA[img][c] = a;
    g_bnB[img][c] = beta[c] - mean * a;
  }
}

// ---------------- grouped 3x3 conv: 8oc x 4w per thread (R4, kept) -----------
#define IN_ST 132
#define CONV_SMEM ((CG*6*IN_ST + CG*CG*9)*4)

template<bool FIRST>
__global__ __launch_bounds__(256, 3) void conv3x3_kernel(
    const float* __restrict__ xL, const float* __restrict__ xR,
    float* __restrict__ t1, float* __restrict__ t2,
    const float* __restrict__ wgt, const float* __restrict__ bias) {
  extern __shared__ float sm[];
  float* in_s = sm;                 // [16ic][6r][132]
  float* w_s  = sm + CG*6*IN_ST;    // [ic][kh][kw][16oc]
  int t = threadIdx.x;
  int img = blockIdx.z;
  int b = blockIdx.y >> 2, g = blockIdx.y & 3;
  int h0 = blockIdx.x * 4;
  const float* xorig = img ? xR : xL;
  const float* xin = FIRST ? xorig : (t1 + (size_t)img*IMG);
  float* out = (FIRST ? t1 : t2) + (size_t)img*IMG;

  for (int i = t; i < CG*CG*9; i += 256) {
    int oc = i / 144, r = i - oc*144;
    w_s[r*16 + oc] = wgt[g*CG*CG*9 + i];
  }
  for (int i = t; i < CG*6*IN_ST; i += 256) {
    int ic  = i / (6*IN_ST);
    int rem = i - ic*(6*IN_ST);
    int r   = rem / IN_ST;
    int wc  = rem - r*IN_ST;
    int hh  = h0 - 1 + r;
    int ww  = wc - 1;
    float v = 0.f;
    if ((unsigned)hh < (unsigned)NH && (unsigned)ww < (unsigned)NW) {
      v = xin[((size_t)(b*NC + g*CG + ic)*NH + hh)*NW + ww];
      if (FIRST) v = g_bnA[img][g*CG+ic]*v + g_bnB[img][g*CG+ic];
    }
    in_s[i] = v;
  }
  __syncthreads();

  int wseg = t & 31, hh2 = (t >> 5) & 3, ocq = t >> 7;
  int w0 = wseg * 4, oc0 = ocq * 8;

  u64 acc2[4][4];
  #pragma unroll
  for (int p = 0; p < 4; p++) {
    u64 bz = f2pk(bias[g*CG+oc0+2*p], bias[g*CG+oc0+2*p+1]);
    #pragma unroll
    for (int j = 0; j < 4; j++) acc2[p][j] = bz;
  }

  for (int ic = 0; ic < CG; ic++) {
    #pragma unroll
    for (int kh = 0; kh < 3; kh++) {
      const float* row = in_s + (ic*6 + hh2 + kh)*IN_ST + w0;
      float4 A  = *(const float4*)row;
      float2 C2 = *(const float2*)(row + 4);
      u64 ind[6];
      ind[0]=f2dup(A.x); ind[1]=f2dup(A.y); ind[2]=f2dup(A.z);
      ind[3]=f2dup(A.w); ind[4]=f2dup(C2.x); ind[5]=f2dup(C2.y);
      #pragma unroll
      for (int kw = 0; kw < 3; kw++) {
        const float* wb = &w_s[((ic*3+kh)*3 + kw)*16 + oc0];
        ulonglong2 wA = *(const ulonglong2*)wb;
        ulonglong2 wB = *(const ulonglong2*)(wb + 4);
        #pragma unroll
        for (int j = 0; j < 4; j++) {
          fma2(acc2[0][j], ind[kw+j], wA.x);
          fma2(acc2[1][j], ind[kw+j], wA.y);
          fma2(acc2[2][j], ind[kw+j], wB.x);
          fma2(acc2[3][j], ind[kw+j], wB.y);
        }
      }
    }
  }

  int hout = h0 + hh2;
  #pragma unroll
  for (int o = 0; o < 8; o++) {
    int ch = g*CG + oc0 + o;
    size_t idx = ((size_t)(b*NC + ch)*NH + hout)*NW + w0;
    float r[4];
    #pragma unroll
    for (int j = 0; j < 4; j++) {
      float2 f = f2up(acc2[o>>1][j]);
      r[j] = (o & 1) ? f.y : f.x;
    }
    if (FIRST) {
      #pragma unroll
      for (int j = 0; j < 4; j++) r[j] = r[j] > 0.f ? r[j] : 0.1f*r[j];
    } else {
      float ra = g_bnA[img][ch], rb = g_bnB[img][ch];
      float4 x0 = *(const float4*)&xorig[idx];
      float xs[4] = {x0.x,x0.y,x0.z,x0.w};
      #pragma unroll
      for (int j = 0; j < 4; j++) r[j] = r[j] + ra*xs[j] + rb;
    }
    *(float4*)&out[idx] = make_float4(r[0],r[1],r[2],r[3]);
  }
}

// ---------------- fused attention (R3 tiling + rank-1 softmax) ---------------
#define ST 128
#define XST 68
#define OFF_BM    16384
#define OFF_XLS   32768
#define OFF_XRS   41472
#define OFF_WS    50176
#define OFF_BS    52224
#define OFF_RMAX  52352
#define OFF_RSUMI 52480
#define OFF_CMAX  52608
#define OFF_CSUMI 52736
#define OFF_VL    52864
#define OFF_VR    52992
#define OFF_PART  53120
#define OFF_FR    55168
#define OFF_GC    55296
#define OFF_MG    55424
#define ATTN_SMEM ((55424 + 32)*4)

__global__ __launch_bounds__(512, 1) void attn_kernel(
    const float* __restrict__ t2, const float* __restrict__ xL,
    const float* __restrict__ xR,
    const float* __restrict__ qw, const float* __restrict__ qb,
    const float* __restrict__ kw_, const float* __restrict__ kb,
    float* __restrict__ outL, float* __restrict__ outR) {
  extern __shared__ float sm[];
  float* Am    = sm;               // t2 stage -> S -> E_rl (row-major)
  float* Bm    = sm + OFF_BM;      // Q/K (k-major) -> E_lr^T
  float* xls   = sm + OFF_XLS;     // [v][c] stride 68
  float* xrs   = sm + OFF_XRS;
  float* ws    = sm + OFF_WS;
  float* bs    = sm + OFF_BS;
  float* rmax  = sm + OFF_RMAX;
  float* rsumI = sm + OFF_RSUMI;
  float* cmax  = sm + OFF_CMAX;
  float* csumI = sm + OFF_CSUMI;
  float* Vl    = sm + OFF_VL;
  float* Vr    = sm + OFF_VR;
  float* part  = sm + OFF_PART;    // 2048
  float* fr    = sm + OFF_FR;
  float* gc    = sm + OFF_GC;
  float* Mg    = sm + OFF_MG;
  int n = blockIdx.x, b = n >> 7, h = n & 127;
  int t = threadIdx.x, warp = t >> 5, lane = t & 31;

  // stage weights/bias + both t2 rows
  for (int i = t; i < 2048; i += 512) ws[i] = (i < 1024) ? qw[i] : kw_[i-1024];
  if (t < 128) bs[t] = (t < 64) ? qb[t] : kb[t-64];
  for (int i = t; i < 16384; i += 512) {
    int c = i >> 7, u = i & 127;
    size_t gi = ((c >= 64) ? (size_t)IMG : 0) +
                ((size_t)(b*NC + (c & 63))*NH + h)*NW + u;
    Am[c*ST + u] = t2[gi];
  }
  __syncthreads();

  // 1x1 grouped conv (f32x2, pairs over u): Bm[k][u]
  for (int i = t; i < 8192; i += 512) {
    int k = i >> 6, up = (i & 63)*2;
    int cb = (k >> 4) * 16;
    float bzv = bs[k];
    u64 a = f2pk(bzv, bzv);
    #pragma unroll
    for (int ic = 0; ic < 16; ic++) {
      u64 w2 = f2dup(ws[k*16 + ic]);
      u64 xp = *(const u64*)&Am[(cb + ic)*ST + up];
      fma2(a, w2, xp);
    }
    *(u64*)&Bm[k*ST + up] = a;
  }
  __syncthreads();

  // row-mean subtract
  for (int r = warp; r < 128; r += 16) {
    float s = 0.f;
    for (int u = lane; u < 128; u += 32) s += Bm[r*ST + u];
    #pragma unroll
    for (int off = 16; off; off >>= 1) s += __shfl_xor_sync(0xffffffffu, s, off);
    float mean = s * (1.f/128.f);
    for (int u = lane; u < 128; u += 32) Bm[r*ST + u] -= mean;
  }
  __syncthreads();

  // GEMM1: S[u][v] = sum_k Q[k][u]*K[k][v]  (R3 tiling: 8u x 4v)
  {
    int u0 = (t >> 5) * 8, v0 = (t & 31) * 4;
    u64 acc2[8][2];
    #pragma unroll
    for (int i = 0; i < 8; i++) { acc2[i][0] = 0ull; acc2[i][1] = 0ull; }
    for (int k = 0; k < 64; k++) {
      float4 qa  = *(const float4*)&Bm[k*ST + u0];
      float4 qb4 = *(const float4*)&Bm[k*ST + u0 + 4];
      ulonglong2 kv = *(const ulonglong2*)&Bm[(64+k)*ST + v0];
      float qv[8] = {qa.x,qa.y,qa.z,qa.w,qb4.x,qb4.y,qb4.z,qb4.w};
      #pragma unroll
      for (int i = 0; i < 8; i++) {
        u64 qd = f2dup(qv[i]);
        fma2(acc2[i][0], qd, kv.x);
        fma2(acc2[i][1], qd, kv.y);
      }
    }
    #pragma unroll
    for (int i = 0; i < 8; i++) {
      float2 a = f2up(acc2[i][0]), c = f2up(acc2[i][1]);
      *(float4*)&Am[(u0+i)*ST + v0] = make_float4(a.x,a.y,c.x,c.y);
    }
  }
  __syncthreads();

  // Phase A: maxes + x staging (warp-specialized)
  if (warp < 8) {                     // row maxes
    for (int r = warp*16; r < warp*16 + 16; r++) {
      float m = -1e30f;
      for (int j = lane; j < 128; j += 32) m = fmaxf(m, Am[r*ST + j]);
      #pragma unroll
      for (int off = 16; off; off >>= 1) m = fmaxf(m, __shfl_xor_sync(0xffffffffu, m, off));
      if (lane == 0) rmax[r] = m;
    }
  } else if (warp < 12) {             // column maxes
    int col = (warp - 8)*32 + lane;
    float m0=-1e30f, m1=-1e30f, m2=-1e30f, m3=-1e30f;
    for (int r = 0; r < 128; r += 4) {
      m0 = fmaxf(m0, Am[(r+0)*ST + col]);
      m1 = fmaxf(m1, Am[(r+1)*ST + col]);
      m2 = fmaxf(m2, Am[(r+2)*ST + col]);
      m3 = fmaxf(m3, Am[(r+3)*ST + col]);
    }
    cmax[col] = fmaxf(fmaxf(m0,m1), fmaxf(m2,m3));
  } else {                            // stage x rows [v][c]
    for (int i = t - 384; i < 8192; i += 128) {
      int c = i >> 7, v = i & 127;
      size_t gi = ((size_t)(b*NC + c)*NH + h)*NW + v;
      xls[v*XST + c] = xL[gi];
      xrs[v*XST + c] = xR[gi];
    }
  }
  __syncthreads();

  // global max + rank-1 softmax factors
  if (t < 32) {
    float m = fmaxf(fmaxf(rmax[t], rmax[t+32]), fmaxf(rmax[t+64], rmax[t+96]));
    #pragma unroll
    for (int off = 16; off; off >>= 1) m = fmaxf(m, __shfl_xor_sync(0xffffffffu, m, off));
    if (t == 0) Mg[0] = m;
  }
  __syncthreads();
  if (t < 128) {
    float M = Mg[0];
    fr[t] = __expf(rmax[t] - M);
    gc[t] = __expf(M - cmax[t]);
  }
  __syncthreads();

  // Phase B: one exp per element; E_lr derived by rank-1 multiply
  {
    float gcv[4];
    #pragma unroll
    for (int k = 0; k < 4; k++) gcv[k] = gc[lane + k*32];
    float csump[4] = {0.f, 0.f, 0.f, 0.f};
    for (int rr = 0; rr < 8; rr++) {
      int r = warp*8 + rr;
      float rm = rmax[r];
      float frv = fr[r];
      float rs = 0.f;
      #pragma unroll
      for (int k = 0; k < 4; k++) {
        int c = lane + k*32;
        float e = __expf(Am[r*ST + c] - rm);
        Am[r*ST + c] = e;
        float el = e * (frv * gcv[k]);
        Bm[r*ST + c] = el;
        rs += e;
        csump[k] += el;
      }
      #pragma unroll
      for (int off = 16; off; off >>= 1) rs += __shfl_xor_sync(0xffffffffu, rs, off);
      if (lane == 0) rsumI[r] = 1.f / rs;
    }
    #pragma unroll
    for (int k = 0; k < 4; k++) part[warp*128 + k*32 + lane] = csump[k];
  }
  __syncthreads();
  if (t < 128) {
    float s = 0.f;
    #pragma unroll
    for (int w = 0; w < 16; w++) s += part[w*128 + t];
    csumI[t] = 1.f / s;
  }
  __syncthreads();

  // V_left[u] = sum_v (sum_d rsumI[u+d]*E_rl[u+d][v]) * E_lr^T[u][v]*csumI[v]
  for (int u = warp; u < 128; u += 16) {
    float rI[5];
    #pragma unroll
    for (int d = 0; d < 5; d++) {
      int ui = u + d - 2;
      rI[d] = ((unsigned)ui < 128u) ? rsumI[ui] : 0.f;
    }
    float acc = 0.f;
    for (int v = lane; v < 128; v += 32) {
      float s5 = 0.f;
      #pragma unroll
      for (int d = 0; d < 5; d++) {
        int ui = u + d - 2;
        if ((unsigned)ui < 128u) s5 += rI[d]*Am[ui*ST + v];
      }
      acc += s5 * Bm[u*ST + v] * csumI[v];
    }
    #pragma unroll
    for (int off = 16; off; off >>= 1) acc += __shfl_xor_sync(0xffffffffu, acc, off);
    if (lane == 0) Vl[u] = tanhf(5.f*acc);
  }
  // V_right[u] = sum_v E_rl[v][u]*rsumI[v] * (sum_d E_lr^T[v][u+d]*csumI[u+d])
  {
    int u = (warp & 3)*32 + lane;
    int v0 = (warp >> 2)*32;
    float ci[5];
    #pragma unroll
    for (int d = 0; d < 5; d++) {
      int ui = u + d - 2;
      ci[d] = ((unsigned)ui < 128u) ? csumI[ui] : 0.f;
    }
    float acc = 0.f;
    for (int v = v0; v < v0 + 32; v++) {
      float s5 = 0.f;
      #pragma unroll
      for (int d = 0; d < 5; d++) {
        int ui = u + d - 2;
        if ((unsigned)ui < 128u) s5 += Bm[v*ST + ui]*ci[d];
      }
      acc += Am[v*ST + u] * rsumI[v] * s5;
    }
    part[(warp >> 2)*128 + u] = acc;
  }
  __syncthreads();
  if (t < 128) Vr[t] = tanhf(5.f*(part[t] + part[128+t] + part[256+t] + part[384+t]));

  // GEMM2 (g0): xlT[u][c] = rsumI[u]*sum_v E_rl[u][v]*xr[v][c]   (R3 tiling)
  // GEMM3 (g1): xrT[u][c] = csumI[u]*sum_v E_lr^T[v][u]*xl[v][c]
  int group = t >> 8;
  int tid = t & 255;
  int c0 = (tid & 15)*4, u0 = (tid >> 4)*8;
  u64 acc2[8][2];
  #pragma unroll
  for (int i = 0; i < 8; i++) { acc2[i][0] = 0ull; acc2[i][1] = 0ull; }

  if (group == 0) {
    for (int v0g = 0; v0g < 128; v0g += 4) {
      ulonglong2 x0 = *(const ulonglong2*)&xrs[(v0g+0)*XST + c0];
      ulonglong2 x1 = *(const ulonglong2*)&xrs[(v0g+1)*XST + c0];
      ulonglong2 x2 = *(const ulonglong2*)&xrs[(v0g+2)*XST + c0];
      ulonglong2 x3 = *(const ulonglong2*)&xrs[(v0g+3)*XST + c0];
      #pragma unroll
      for (int i = 0; i < 8; i++) {
        float4 m = *(const float4*)&Am[(u0+i)*ST + v0g];
        u64 m0 = f2dup(m.x), m1 = f2dup(m.y), m2 = f2dup(m.z), m3 = f2dup(m.w);
        fma2(acc2[i][0], m0, x0.x); fma2(acc2[i][1], m0, x0.y);
        fma2(acc2[i][0], m1, x1.x); fma2(acc2[i][1], m1, x1.y);
        fma2(acc2[i][0], m2, x2.x); fma2(acc2[i][1], m2, x2.y);
        fma2(acc2[i][0], m3, x3.x); fma2(acc2[i][1], m3, x3.y);
      }
    }
  } else {
    for (int v = 0; v < 128; v++) {
      ulonglong2 xp = *(const ulonglong2*)&xls[v*XST + c0];
      float4 b0 = *(const float4*)&Bm[v*ST + u0];
      float4 b1 = *(const float4*)&Bm[v*ST + u0 + 4];
      float bu[8] = {b0.x,b0.y,b0.z,b0.w,b1.x,b1.y,b1.z,b1.w};
      #pragma unroll
      for (int i = 0; i < 8; i++) {
        u64 bd = f2dup(bu[i]);
        fma2(acc2[i][0], bd, xp.x);
        fma2(acc2[i][1], bd, xp.y);
      }
    }
  }
  __syncthreads();

  // blend in place (normalization folded)
  if (group == 0) {
    #pragma unroll
    for (int i = 0; i < 8; i++) {
      int u = u0 + i;
      float vl = Vl[u];
      float gsc = vl * rsumI[u];
      float2 f0 = f2up(acc2[i][0]), f1 = f2up(acc2[i][1]);
      float xt[4] = {f0.x, f0.y, f1.x, f1.y};
      #pragma unroll
      for (int cc = 0; cc < 4; cc++) {
        int x = u*XST + c0 + cc;
        xls[x] = xls[x]*(1.f - vl) + xt[cc]*gsc;
      }
    }
  } else {
    #pragma unroll
    for (int i = 0; i < 8; i++) {
      int u = u0 + i;
      float vr = Vr[u];
      float gsc = vr * csumI[u];
      float2 f0 = f2up(acc2[i][0]), f1 = f2up(acc2[i][1]);
      float xt[4] = {f0.x, f0.y, f1.x, f1.y};
      #pragma unroll
      for (int cc = 0; cc < 4; cc++) {
        int x = u*XST + c0 + cc;
        xrs[x] = xrs[x]*(1.f - vr) + xt[cc]*gsc;
      }
    }
  }
  __syncthreads();

  for (int i = t; i < 8192; i += 512) {
    int c = i >> 7, u = i & 127;
    size_t gi = ((size_t)(b*NC + c)*NH + h)*NW + u;
    outL[gi] = xls[u*XST + c];
    outR[gi] = xrs[u*XST + c];
  }
}

// ---------------- host ------------------------------------------------------
extern "C" void kernel_launch(void* const* d_in, const int* in_sizes, int n_in,
                              void* d_out, int out_size) {
  const float* xL    = (const float*)d_in[0];
  const float* xR    = (const float*)d_in[1];
  const float* gamma = (const float*)d_in[2];
  const float* beta  = (const float*)d_in[3];
  const float* w1    = (const float*)d_in[4];
  const float* b1    = (const float*)d_in[5];
  const float* w2    = (const float*)d_in[6];
  const float* b2    = (const float*)d_in[7];
  const float* qw    = (const float*)d_in[8];
  const float* qb    = (const float*)d_in[9];
  const float* kw    = (const float*)d_in[10];
  const float* kb    = (const float*)d_in[11];
  float* outL = (float*)d_out;
  float* outR = outL + (size_t)IMG;

  float *t1, *t2;
  cudaGetSymbolAddress((void**)&t1, g_t1);
  cudaGetSymbolAddress((void**)&t2, g_t2);

  cudaFuncSetAttribute(conv3x3_kernel<true>,  cudaFuncAttributeMaxDynamicSharedMemorySize, CONV_SMEM);
  cudaFuncSetAttribute(conv3x3_kernel<false>, cudaFuncAttributeMaxDynamicSharedMemorySize, CONV_SMEM);
  cudaFuncSetAttribute(attn_kernel, cudaFuncAttributeMaxDynamicSharedMemorySize, ATTN_SMEM);

  bn_stats_kernel<<<128, 256>>>(xL, xR, gamma, beta);

  dim3 cgrid(NH/4, NB*NG, 2);
  conv3x3_kernel<true ><<<cgrid, 256, CONV_SMEM>>>(xL, xR, t1, t2, w1, b1);
  conv3x3_kernel<false><<<cgrid, 256, CONV_SMEM>>>(xL, xR, t1, t2, w2, b2);

  attn_kernel<<<NROW, 512, ATTN_SMEM>>>(t2, xL, xR, qw, qb, kw, kb, outL, outR);
}

// round 6
// speedup vs baseline: 1.1615x; 1.0248x over previous
#include <cuda_runtime.h>
#include <math.h>

#define NB 8
#define NC 64
#define NG 4
#define CG 16
#define NH 128
#define NW 128
#define HW (NH*NW)
#define IMG (NB*NC*HW)
#define NROW (NB*NH)

typedef unsigned long long u64;

__device__ __forceinline__ u64 f2dup(float v) {
  u64 r; asm("mov.b64 %0, {%1, %1};" : "=l"(r) : "f"(v)); return r;
}
__device__ __forceinline__ u64 f2pk(float a, float b) {
  u64 r; asm("mov.b64 %0, {%1, %2};" : "=l"(r) : "f"(a), "f"(b)); return r;
}
__device__ __forceinline__ void fma2(u64& d, u64 a, u64 b) {
  asm("fma.rn.f32x2 %0, %1, %2, %0;" : "+l"(d) : "l"(a), "l"(b));
}
__device__ __forceinline__ float2 f2up(u64 v) {
  float2 f; asm("mov.b64 {%0, %1}, %2;" : "=f"(f.x), "=f"(f.y) : "l"(v)); return f;
}

// ---------------- scratch ----------------------------------------------------
__device__ float g_t1[2*(size_t)IMG];
__device__ float g_t2[2*(size_t)IMG];
__device__ float g_bnA[2][NC];
__device__ float g_bnB[2][NC];

// ---------------- BN statistics ----------------------------------------------
__global__ __launch_bounds__(256) void bn_stats_kernel(
    const float* __restrict__ xl, const float* __restrict__ xr,
    const float* __restrict__ gamma, const float* __restrict__ beta) {
  int c = blockIdx.x & 63;
  int img = blockIdx.x >> 6;
  const float4* x = (const float4*)(img ? xr : xl);
  int t = threadIdx.x;
  float s = 0.f, s2 = 0.f;
  for (int b = 0; b < NB; b++) {
    const float4* p = x + (size_t)(b*NC + c)*(HW/4);
    for (int i = t; i < HW/4; i += 256) {
      float4 v = p[i];
      s  += v.x + v.y + v.z + v.w;
      s2 += v.x*v.x + v.y*v.y + v.z*v.z + v.w*v.w;
    }
  }
  __shared__ float sh[256], sh2[256];
  sh[t] = s; sh2[t] = s2; __syncthreads();
  for (int off = 128; off; off >>= 1) {
    if (t < off) { sh[t] += sh[t+off]; sh2[t] += sh2[t+off]; }
    __syncthreads();
  }
  if (t == 0) {
    const float inv = 1.f / (float)(NB*HW);
    float mean = sh[0] * inv;
    float var  = sh2[0] * inv - mean*mean;
    float a = gamma[c] * rsqrtf(var + 1e-5f);
    g_bnA[img][c] = a;
    g_bnB[img][c] = beta[c] - mean * a;
  }
}

// ---------------- grouped 3x3 conv: 8oc x 4w per thread (kept) ---------------
#define IN_ST 132
#define CONV_SMEM ((CG*6*IN_ST + CG*CG*9)*4)

template<bool FIRST>
__global__ __launch_bounds__(256, 3) void conv3x3_kernel(
    const float* __restrict__ xL, const float* __restrict__ xR,
    float* __restrict__ t1, float* __restrict__ t2,
    const float* __restrict__ wgt, const float* __restrict__ bias) {
  extern __shared__ float sm[];
  float* in_s = sm;                 // [16ic][6r][132]
  float* w_s  = sm + CG*6*IN_ST;    // [ic][kh][kw][16oc]
  int t = threadIdx.x;
  int img = blockIdx.z;
  int b = blockIdx.y >> 2, g = blockIdx.y & 3;
  int h0 = blockIdx.x * 4;
  const float* xorig = img ? xR : xL;
  const float* xin = FIRST ? xorig : (t1 + (size_t)img*IMG);
  float* out = (FIRST ? t1 : t2) + (size_t)img*IMG;

  for (int i = t; i < CG*CG*9; i += 256) {
    int oc = i / 144, r = i - oc*144;
    w_s[r*16 + oc] = wgt[g*CG*CG*9 + i];
  }
  for (int i = t; i < CG*6*IN_ST; i += 256) {
    int ic  = i / (6*IN_ST);
    int rem = i - ic*(6*IN_ST);
    int r   = rem / IN_ST;
    int wc  = rem - r*IN_ST;
    int hh  = h0 - 1 + r;
    int ww  = wc - 1;
    float v = 0.f;
    if ((unsigned)hh < (unsigned)NH && (unsigned)ww < (unsigned)NW) {
      v = xin[((size_t)(b*NC + g*CG + ic)*NH + hh)*NW + ww];
      if (FIRST) v = g_bnA[img][g*CG+ic]*v + g_bnB[img][g*CG+ic];
    }
    in_s[i] = v;
  }
  __syncthreads();

  int wseg = t & 31, hh2 = (t >> 5) & 3, ocq = t >> 7;
  int w0 = wseg * 4, oc0 = ocq * 8;

  u64 acc2[4][4];
  #pragma unroll
  for (int p = 0; p < 4; p++) {
    u64 bz = f2pk(bias[g*CG+oc0+2*p], bias[g*CG+oc0+2*p+1]);
    #pragma unroll
    for (int j = 0; j < 4; j++) acc2[p][j] = bz;
  }

  for (int ic = 0; ic < CG; ic++) {
    #pragma unroll
    for (int kh = 0; kh < 3; kh++) {
      const float* row = in_s + (ic*6 + hh2 + kh)*IN_ST + w0;
      float4 A  = *(const float4*)row;
      float2 C2 = *(const float2*)(row + 4);
      u64 ind[6];
      ind[0]=f2dup(A.x); ind[1]=f2dup(A.y); ind[2]=f2dup(A.z);
      ind[3]=f2dup(A.w); ind[4]=f2dup(C2.x); ind[5]=f2dup(C2.y);
      #pragma unroll
      for (int kw = 0; kw < 3; kw++) {
        const float* wb = &w_s[((ic*3+kh)*3 + kw)*16 + oc0];
        ulonglong2 wA = *(const ulonglong2*)wb;
        ulonglong2 wB = *(const ulonglong2*)(wb + 4);
        #pragma unroll
        for (int j = 0; j < 4; j++) {
          fma2(acc2[0][j], ind[kw+j], wA.x);
          fma2(acc2[1][j], ind[kw+j], wA.y);
          fma2(acc2[2][j], ind[kw+j], wB.x);
          fma2(acc2[3][j], ind[kw+j], wB.y);
        }
      }
    }
  }

  int hout = h0 + hh2;
  #pragma unroll
  for (int o = 0; o < 8; o++) {
    int ch = g*CG + oc0 + o;
    size_t idx = ((size_t)(b*NC + ch)*NH + hout)*NW + w0;
    float r[4];
    #pragma unroll
    for (int j = 0; j < 4; j++) {
      float2 f = f2up(acc2[o>>1][j]);
      r[j] = (o & 1) ? f.y : f.x;
    }
    if (FIRST) {
      #pragma unroll
      for (int j = 0; j < 4; j++) r[j] = r[j] > 0.f ? r[j] : 0.1f*r[j];
    } else {
      float ra = g_bnA[img][ch], rb = g_bnB[img][ch];
      float4 x0 = *(const float4*)&xorig[idx];
      float xs[4] = {x0.x,x0.y,x0.z,x0.w};
      #pragma unroll
      for (int j = 0; j < 4; j++) r[j] = r[j] + ra*xs[j] + rb;
    }
    *(float4*)&out[idx] = make_float4(r[0],r[1],r[2],r[3]);
  }
}

// ---------------- fused attention (1024 threads, 32 warps) -------------------
#define ST 128
#define XST 68
#define OFF_BM    16384
#define OFF_XLS   32768
#define OFF_XRS   41472
#define OFF_WS    50176
#define OFF_BS    52224
#define OFF_RMAX  52352
#define OFF_RSUMI 52480
#define OFF_CMAX  52608
#define OFF_CSUMI 52736
#define OFF_VL    52864
#define OFF_VR    52992
#define OFF_PART  53120
#define OFF_FR    55168
#define OFF_GC    55296
#define OFF_MG    55424
#define ATTN_SMEM ((55424 + 32)*4)

__global__ __launch_bounds__(1024, 1) void attn_kernel(
    const float* __restrict__ t2, const float* __restrict__ xL,
    const float* __restrict__ xR,
    const float* __restrict__ qw, const float* __restrict__ qb,
    const float* __restrict__ kw_, const float* __restrict__ kb,
    float* __restrict__ outL, float* __restrict__ outR) {
  extern __shared__ float sm[];
  float* Am    = sm;               // t2 stage -> S -> E_rl (row-major)
  float* Bm    = sm + OFF_BM;      // Q/K (k-major) -> E_lr^T
  float* xls   = sm + OFF_XLS;     // [v][c] stride 68
  float* xrs   = sm + OFF_XRS;
  float* ws    = sm + OFF_WS;
  float* bs    = sm + OFF_BS;
  float* rmax  = sm + OFF_RMAX;
  float* rsumI = sm + OFF_RSUMI;
  float* cmax  = sm + OFF_CMAX;
  float* csumI = sm + OFF_CSUMI;
  float* Vl    = sm + OFF_VL;
  float* Vr    = sm + OFF_VR;
  float* part  = sm + OFF_PART;    // 2048 floats
  float* fr    = sm + OFF_FR;
  float* gc    = sm + OFF_GC;
  float* Mg    = sm + OFF_MG;
  int n = blockIdx.x, b = n >> 7, h = n & 127;
  int t = threadIdx.x, warp = t >> 5, lane = t & 31;

  // stage weights/bias + both t2 rows
  for (int i = t; i < 2048; i += 1024) ws[i] = (i < 1024) ? qw[i] : kw_[i-1024];
  if (t < 128) bs[t] = (t < 64) ? qb[t] : kb[t-64];
  for (int i = t; i < 16384; i += 1024) {
    int c = i >> 7, u = i & 127;
    size_t gi = ((c >= 64) ? (size_t)IMG : 0) +
                ((size_t)(b*NC + (c & 63))*NH + h)*NW + u;
    Am[c*ST + u] = t2[gi];
  }
  __syncthreads();

  // 1x1 grouped conv (f32x2, pairs over u): Bm[k][u]
  for (int i = t; i < 8192; i += 1024) {
    int k = i >> 6, up = (i & 63)*2;
    int cb = (k >> 4) * 16;
    float bzv = bs[k];
    u64 a = f2pk(bzv, bzv);
    #pragma unroll
    for (int ic = 0; ic < 16; ic++) {
      u64 w2 = f2dup(ws[k*16 + ic]);
      u64 xp = *(const u64*)&Am[(cb + ic)*ST + up];
      fma2(a, w2, xp);
    }
    *(u64*)&Bm[k*ST + up] = a;
  }
  __syncthreads();

  // row-mean subtract
  for (int r = warp; r < 128; r += 32) {
    float s = 0.f;
    for (int u = lane; u < 128; u += 32) s += Bm[r*ST + u];
    #pragma unroll
    for (int off = 16; off; off >>= 1) s += __shfl_xor_sync(0xffffffffu, s, off);
    float mean = s * (1.f/128.f);
    for (int u = lane; u < 128; u += 32) Bm[r*ST + u] -= mean;
  }
  __syncthreads();

  // GEMM1: S[u][v] = sum_k Q[k][u]*K[k][v]   (4u x 4v per thread)
  {
    int u0 = warp * 4, v0 = lane * 4;
    u64 acc2[4][2];
    #pragma unroll
    for (int i = 0; i < 4; i++) { acc2[i][0] = 0ull; acc2[i][1] = 0ull; }
    for (int k = 0; k < 64; k++) {
      float4 qv = *(const float4*)&Bm[k*ST + u0];          // warp broadcast
      ulonglong2 kv = *(const ulonglong2*)&Bm[(64+k)*ST + v0];
      u64 q0 = f2dup(qv.x), q1 = f2dup(qv.y), q2 = f2dup(qv.z), q3 = f2dup(qv.w);
      fma2(acc2[0][0], q0, kv.x); fma2(acc2[0][1], q0, kv.y);
      fma2(acc2[1][0], q1, kv.x); fma2(acc2[1][1], q1, kv.y);
      fma2(acc2[2][0], q2, kv.x); fma2(acc2[2][1], q2, kv.y);
      fma2(acc2[3][0], q3, kv.x); fma2(acc2[3][1], q3, kv.y);
    }
    #pragma unroll
    for (int i = 0; i < 4; i++) {
      float2 a = f2up(acc2[i][0]), c = f2up(acc2[i][1]);
      *(float4*)&Am[(u0+i)*ST + v0] = make_float4(a.x,a.y,c.x,c.y);
    }
  }
  __syncthreads();

  // Phase A: maxes + x staging (warp-specialized)
  if (warp < 16) {                    // row maxes: 8 rows/warp
    for (int r = warp*8; r < warp*8 + 8; r++) {
      float m = -1e30f;
      for (int j = lane; j < 128; j += 32) m = fmaxf(m, Am[r*ST + j]);
      #pragma unroll
      for (int off = 16; off; off >>= 1) m = fmaxf(m, __shfl_xor_sync(0xffffffffu, m, off));
      if (lane == 0) rmax[r] = m;
    }
  } else if (warp < 20) {             // column maxes
    int col = (warp - 16)*32 + lane;
    float m0=-1e30f, m1=-1e30f, m2=-1e30f, m3=-1e30f;
    for (int r = 0; r < 128; r += 4) {
      m0 = fmaxf(m0, Am[(r+0)*ST + col]);
      m1 = fmaxf(m1, Am[(r+1)*ST + col]);
      m2 = fmaxf(m2, Am[(r+2)*ST + col]);
      m3 = fmaxf(m3, Am[(r+3)*ST + col]);
    }
    cmax[col] = fmaxf(fmaxf(m0,m1), fmaxf(m2,m3));
  } else {                            // stage x rows [v][c]: 12 warps
    for (int i = t - 640; i < 8192; i += 384) {
      int c = i >> 7, v = i & 127;
      size_t gi = ((size_t)(b*NC + c)*NH + h)*NW + v;
      xls[v*XST + c] = xL[gi];
      xrs[v*XST + c] = xR[gi];
    }
  }
  __syncthreads();

  // global max + rank-1 softmax factors
  if (t < 32) {
    float m = fmaxf(fmaxf(rmax[t], rmax[t+32]), fmaxf(rmax[t+64], rmax[t+96]));
    #pragma unroll
    for (int off = 16; off; off >>= 1) m = fmaxf(m, __shfl_xor_sync(0xffffffffu, m, off));
    if (t == 0) Mg[0] = m;
  }
  __syncthreads();
  if (t < 128) {
    float M = Mg[0];
    fr[t] = __expf(rmax[t] - M);
    gc[t] = __expf(M - cmax[t]);
  }
  __syncthreads();

  // Phase B (warps 0-15): one exp per element; E_lr by rank-1 multiply
  if (warp < 16) {
    float gcv[4];
    #pragma unroll
    for (int k = 0; k < 4; k++) gcv[k] = gc[lane + k*32];
    float csump[4] = {0.f, 0.f, 0.f, 0.f};
    for (int rr = 0; rr < 8; rr++) {
      int r = warp*8 + rr;
      float rm = rmax[r];
      float frv = fr[r];
      float rs = 0.f;
      #pragma unroll
      for (int k = 0; k < 4; k++) {
        int c = lane + k*32;
        float e = __expf(Am[r*ST + c] - rm);
        Am[r*ST + c] = e;
        float el = e * (frv * gcv[k]);
        Bm[r*ST + c] = el;
        rs += e;
        csump[k] += el;
      }
      #pragma unroll
      for (int off = 16; off; off >>= 1) rs += __shfl_xor_sync(0xffffffffu, rs, off);
      if (lane == 0) rsumI[r] = 1.f / rs;
    }
    #pragma unroll
    for (int k = 0; k < 4; k++) part[warp*128 + k*32 + lane] = csump[k];
  }
  __syncthreads();
  if (t < 128) {
    float s = 0.f;
    #pragma unroll
    for (int w = 0; w < 16; w++) s += part[w*128 + t];
    csumI[t] = 1.f / s;
  }
  __syncthreads();

  // V_left[u] = sum_v (sum_d rsumI[u+d]*E_rl[u+d][v]) * E_lr^T[u][v]*csumI[v]
  for (int u = warp; u < 128; u += 32) {
    float rI[5];
    #pragma unroll
    for (int d = 0; d < 5; d++) {
      int ui = u + d - 2;
      rI[d] = ((unsigned)ui < 128u) ? rsumI[ui] : 0.f;
    }
    float acc = 0.f;
    for (int v = lane; v < 128; v += 32) {
      float s5 = 0.f;
      #pragma unroll
      for (int d = 0; d < 5; d++) {
        int ui = u + d - 2;
        if ((unsigned)ui < 128u) s5 += rI[d]*Am[ui*ST + v];
      }
      acc += s5 * Bm[u*ST + v] * csumI[v];
    }
    #pragma unroll
    for (int off = 16; off; off >>= 1) acc += __shfl_xor_sync(0xffffffffu, acc, off);
    if (lane == 0) Vl[u] = tanhf(5.f*acc);
  }
  // V_right[u] = sum_v E_rl[v][u]*rsumI[v] * (sum_d E_lr^T[v][u+d]*csumI[u+d])
  {
    int u = (warp & 3)*32 + lane;
    int v0 = (warp >> 2)*16;          // 8 v-blocks of 16
    float ci[5];
    #pragma unroll
    for (int d = 0; d < 5; d++) {
      int ui = u + d - 2;
      ci[d] = ((unsigned)ui < 128u) ? csumI[ui] : 0.f;
    }
    float acc = 0.f;
    for (int v = v0; v < v0 + 16; v++) {
      float s5 = 0.f;
      #pragma unroll
      for (int d = 0; d < 5; d++) {
        int ui = u + d - 2;
        if ((unsigned)ui < 128u) s5 += Bm[v*ST + ui]*ci[d];
      }
      acc += Am[v*ST + u] * rsumI[v] * s5;
    }
    part[(warp >> 2)*128 + u] = acc;
  }
  __syncthreads();
  if (t < 128) {
    float s = 0.f;
    #pragma unroll
    for (int p = 0; p < 8; p++) s += part[p*128 + t];
    Vr[t] = tanhf(5.f*s);
  }

  // GEMM2 (g0, 512 thr): xlT[u][c] = rsumI[u]*sum_v E_rl[u][v]*xr[v][c]  (4u x 4c)
  // GEMM3 (g1, 512 thr): xrT[u][c] = csumI[u]*sum_v E_lr^T[v][u]*xl[v][c]
  int group = t >> 9;
  int tid = t & 511;
  int c0 = (tid & 15)*4, u0 = (tid >> 4)*4;
  u64 acc2[4][2];
  #pragma unroll
  for (int i = 0; i < 4; i++) { acc2[i][0] = 0ull; acc2[i][1] = 0ull; }

  if (group == 0) {
    for (int v0g = 0; v0g < 128; v0g += 4) {
      ulonglong2 x0 = *(const ulonglong2*)&xrs[(v0g+0)*XST + c0];
      ulonglong2 x1 = *(const ulonglong2*)&xrs[(v0g+1)*XST + c0];
      ulonglong2 x2 = *(const ulonglong2*)&xrs[(v0g+2)*XST + c0];
      ulonglong2 x3 = *(const ulonglong2*)&xrs[(v0g+3)*XST + c0];
      #pragma unroll
      for (int i = 0; i < 4; i++) {
        float4 m = *(const float4*)&Am[(u0+i)*ST + v0g];
        u64 m0 = f2dup(m.x), m1 = f2dup(m.y), m2 = f2dup(m.z), m3 = f2dup(m.w);
        fma2(acc2[i][0], m0, x0.x); fma2(acc2[i][1], m0, x0.y);
        fma2(acc2[i][0], m1, x1.x); fma2(acc2[i][1], m1, x1.y);
        fma2(acc2[i][0], m2, x2.x); fma2(acc2[i][1], m2, x2.y);
        fma2(acc2[i][0], m3, x3.x); fma2(acc2[i][1], m3, x3.y);
      }
    }
  } else {
    for (int v = 0; v < 128; v++) {
      ulonglong2 xp = *(const ulonglong2*)&xls[v*XST + c0];
      float4 b0 = *(const float4*)&Bm[v*ST + u0];
      u64 b0d = f2dup(b0.x), b1d = f2dup(b0.y), b2d = f2dup(b0.z), b3d = f2dup(b0.w);
      fma2(acc2[0][0], b0d, xp.x); fma2(acc2[0][1], b0d, xp.y);
      fma2(acc2[1][0], b1d, xp.x); fma2(acc2[1][1], b1d, xp.y);
      fma2(acc2[2][0], b2d, xp.x); fma2(acc2[2][1], b2d, xp.y);
      fma2(acc2[3][0], b3d, xp.x); fma2(acc2[3][1], b3d, xp.y);
    }
  }
  __syncthreads();

  // blend in place (normalization folded)
  if (group == 0) {
    #pragma unroll
    for (int i = 0; i < 4; i++) {
      int u = u0 + i;
      float vl = Vl[u];
      float gsc = vl * rsumI[u];
      float2 f0 = f2up(acc2[i][0]), f1 = f2up(acc2[i][1]);
      float xt[4] = {f0.x, f0.y, f1.x, f1.y};
      #pragma unroll
      for (int cc = 0; cc < 4; cc++) {
        int x = u*XST + c0 + cc;
        xls[x] = xls[x]*(1.f - vl) + xt[cc]*gsc;
      }
    }
  } else {
    #pragma unroll
    for (int i = 0; i < 4; i++) {
      int u = u0 + i;
      float vr = Vr[u];
      float gsc = vr * csumI[u];
      float2 f0 = f2up(acc2[i][0]), f1 = f2up(acc2[i][1]);
      float xt[4] = {f0.x, f0.y, f1.x, f1.y};
      #pragma unroll
      for (int cc = 0; cc < 4; cc++) {
        int x = u*XST + c0 + cc;
        xrs[x] = xrs[x]*(1.f - vr) + xt[cc]*gsc;
      }
    }
  }
  __syncthreads();

  for (int i = t; i < 8192; i += 1024) {
    int c = i >> 7, u = i & 127;
    size_t gi = ((size_t)(b*NC + c)*NH + h)*NW + u;
    outL[gi] = xls[u*XST + c];
    outR[gi] = xrs[u*XST + c];
  }
}

// ---------------- host ------------------------------------------------------
extern "C" void kernel_launch(void* const* d_in, const int* in_sizes, int n_in,
                              void* d_out, int out_size) {
  const float* xL    = (const float*)d_in[0];
  const float* xR    = (const float*)d_in[1];
  const float* gamma = (const float*)d_in[2];
  const float* beta  = (const float*)d_in[3];
  const float* w1    = (const float*)d_in[4];
  const float* b1    = (const float*)d_in[5];
  const float* w2    = (const float*)d_in[6];
  const float* b2    = (const float*)d_in[7];
  const float* qw    = (const float*)d_in[8];
  const float* qb    = (const float*)d_in[9];
  const float* kw    = (const float*)d_in[10];
  const float* kb    = (const float*)d_in[11];
  float* outL = (float*)d_out;
  float* outR = outL + (size_t)IMG;

  float *t1, *t2;
  cudaGetSymbolAddress((void**)&t1, g_t1);
  cudaGetSymbolAddress((void**)&t2, g_t2);

  cudaFuncSetAttribute(conv3x3_kernel<true>,  cudaFuncAttributeMaxDynamicSharedMemorySize, CONV_SMEM);
  cudaFuncSetAttribute(conv3x3_kernel<false>, cudaFuncAttributeMaxDynamicSharedMemorySize, CONV_SMEM);
  cudaFuncSetAttribute(attn_kernel, cudaFuncAttributeMaxDynamicSharedMemorySize, ATTN_SMEM);

  bn_stats_kernel<<<128, 256>>>(xL, xR, gamma, beta);

  dim3 cgrid(NH/4, NB*NG, 2);
  conv3x3_kernel<true ><<<cgrid, 256, CONV_SMEM>>>(xL, xR, t1, t2, w1, b1);
  conv3x3_kernel<false><<<cgrid, 256, CONV_SMEM>>>(xL, xR, t1, t2, w2, b2);

  attn_kernel<<<NROW, 1024, ATTN_SMEM>>>(t2, xL, xR, qw, qb, kw, kb, outL, outR);
}

// round 7
// speedup vs baseline: 1.1688x; 1.0063x over previous
#include <cuda_runtime.h>
#include <math.h>

#define NB 8
#define NC 64
#define NG 4
#define CG 16
#define NH 128
#define NW 128
#define HW (NH*NW)
#define IMG (NB*NC*HW)
#define NROW (NB*NH)

typedef unsigned long long u64;

__device__ __forceinline__ u64 f2dup(float v) {
  u64 r; asm("mov.b64 %0, {%1, %1};" : "=l"(r) : "f"(v)); return r;
}
__device__ __forceinline__ u64 f2pk(float a, float b) {
  u64 r; asm("mov.b64 %0, {%1, %2};" : "=l"(r) : "f"(a), "f"(b)); return r;
}
__device__ __forceinline__ void fma2(u64& d, u64 a, u64 b) {
  asm("fma.rn.f32x2 %0, %1, %2, %0;" : "+l"(d) : "l"(a), "l"(b));
}
__device__ __forceinline__ float2 f2up(u64 v) {
  float2 f; asm("mov.b64 {%0, %1}, %2;" : "=f"(f.x), "=f"(f.y) : "l"(v)); return f;
}

// ---------------- scratch ----------------------------------------------------
__device__ float g_t1[2*(size_t)IMG];
__device__ float g_t2[2*(size_t)IMG];
__device__ float g_bnA[2][NC];
__device__ float g_bnB[2][NC];

// ---------------- BN statistics ----------------------------------------------
__global__ __launch_bounds__(256) void bn_stats_kernel(
    const float* __restrict__ xl, const float* __restrict__ xr,
    const float* __restrict__ gamma, const float* __restrict__ beta) {
  int c = blockIdx.x & 63;
  int img = blockIdx.x >> 6;
  const float4* x = (const float4*)(img ? xr : xl);
  int t = threadIdx.x;
  float s = 0.f, s2 = 0.f;
  for (int b = 0; b < NB; b++) {
    const float4* p = x + (size_t)(b*NC + c)*(HW/4);
    for (int i = t; i < HW/4; i += 256) {
      float4 v = p[i];
      s  += v.x + v.y + v.z + v.w;
      s2 += v.x*v.x + v.y*v.y + v.z*v.z + v.w*v.w;
    }
  }
  __shared__ float sh[256], sh2[256];
  sh[t] = s; sh2[t] = s2; __syncthreads();
  for (int off = 128; off; off >>= 1) {
    if (t < off) { sh[t] += sh[t+off]; sh2[t] += sh2[t+off]; }
    __syncthreads();
  }
  if (t == 0) {
    const float inv = 1.f / (float)(NB*HW);
    float mean = sh[0] * inv;
    float var  = sh2[0] * inv - mean*mean;
    float a = gamma[c] * rsqrtf(var + 1e-5f);
    g_bnA[img][c] = a;
    g_bnB[img][c] = beta[c] - mean * a;
  }
}

// ---------------- grouped 3x3 conv: 8oc x 4w per thread (kept) ---------------
#define IN_ST 132
#define CONV_SMEM ((CG*6*IN_ST + CG*CG*9)*4)

template<bool FIRST>
__global__ __launch_bounds__(256, 3) void conv3x3_kernel(
    const float* __restrict__ xL, const float* __restrict__ xR,
    float* __restrict__ t1, float* __restrict__ t2,
    const float* __restrict__ wgt, const float* __restrict__ bias) {
  extern __shared__ float sm[];
  float* in_s = sm;                 // [16ic][6r][132]
  float* w_s  = sm + CG*6*IN_ST;    // [ic][kh][kw][16oc]
  int t = threadIdx.x;
  int img = blockIdx.z;
  int b = blockIdx.y >> 2, g = blockIdx.y & 3;
  int h0 = blockIdx.x * 4;
  const float* xorig = img ? xR : xL;
  const float* xin = FIRST ? xorig : (t1 + (size_t)img*IMG);
  float* out = (FIRST ? t1 : t2) + (size_t)img*IMG;

  for (int i = t; i < CG*CG*9; i += 256) {
    int oc = i / 144, r = i - oc*144;
    w_s[r*16 + oc] = wgt[g*CG*CG*9 + i];
  }
  for (int i = t; i < CG*6*IN_ST; i += 256) {
    int ic  = i / (6*IN_ST);
    int rem = i - ic*(6*IN_ST);
    int r   = rem / IN_ST;
    int wc  = rem - r*IN_ST;
    int hh  = h0 - 1 + r;
    int ww  = wc - 1;
    float v = 0.f;
    if ((unsigned)hh < (unsigned)NH && (unsigned)ww < (unsigned)NW) {
      v = xin[((size_t)(b*NC + g*CG + ic)*NH + hh)*NW + ww];
      if (FIRST) v = g_bnA[img][g*CG+ic]*v + g_bnB[img][g*CG+ic];
    }
    in_s[i] = v;
  }
  __syncthreads();

  int wseg = t & 31, hh2 = (t >> 5) & 3, ocq = t >> 7;
  int w0 = wseg * 4, oc0 = ocq * 8;

  u64 acc2[4][4];
  #pragma unroll
  for (int p = 0; p < 4; p++) {
    u64 bz = f2pk(bias[g*CG+oc0+2*p], bias[g*CG+oc0+2*p+1]);
    #pragma unroll
    for (int j = 0; j < 4; j++) acc2[p][j] = bz;
  }

  for (int ic = 0; ic < CG; ic++) {
    #pragma unroll
    for (int kh = 0; kh < 3; kh++) {
      const float* row = in_s + (ic*6 + hh2 + kh)*IN_ST + w0;
      float4 A  = *(const float4*)row;
      float2 C2 = *(const float2*)(row + 4);
      u64 ind[6];
      ind[0]=f2dup(A.x); ind[1]=f2dup(A.y); ind[2]=f2dup(A.z);
      ind[3]=f2dup(A.w); ind[4]=f2dup(C2.x); ind[5]=f2dup(C2.y);
      #pragma unroll
      for (int kw = 0; kw < 3; kw++) {
        const float* wb = &w_s[((ic*3+kh)*3 + kw)*16 + oc0];
        ulonglong2 wA = *(const ulonglong2*)wb;
        ulonglong2 wB = *(const ulonglong2*)(wb + 4);
        #pragma unroll
        for (int j = 0; j < 4; j++) {
          fma2(acc2[0][j], ind[kw+j], wA.x);
          fma2(acc2[1][j], ind[kw+j], wA.y);
          fma2(acc2[2][j], ind[kw+j], wB.x);
          fma2(acc2[3][j], ind[kw+j], wB.y);
        }
      }
    }
  }

  int hout = h0 + hh2;
  #pragma unroll
  for (int o = 0; o < 8; o++) {
    int ch = g*CG + oc0 + o;
    size_t idx = ((size_t)(b*NC + ch)*NH + hout)*NW + w0;
    float r[4];
    #pragma unroll
    for (int j = 0; j < 4; j++) {
      float2 f = f2up(acc2[o>>1][j]);
      r[j] = (o & 1) ? f.y : f.x;
    }
    if (FIRST) {
      #pragma unroll
      for (int j = 0; j < 4; j++) r[j] = r[j] > 0.f ? r[j] : 0.1f*r[j];
    } else {
      float ra = g_bnA[img][ch], rb = g_bnB[img][ch];
      float4 x0 = *(const float4*)&xorig[idx];
      float xs[4] = {x0.x,x0.y,x0.z,x0.w};
      #pragma unroll
      for (int j = 0; j < 4; j++) r[j] = r[j] + ra*xs[j] + rb;
    }
    *(float4*)&out[idx] = make_float4(r[0],r[1],r[2],r[3]);
  }
}

// ---------------- fused attention (1024 thr, banded-Gram validity) -----------
#define ST 128
#define XST 68
#define OFF_BM    16384
#define OFF_XLS   32768
#define OFF_XRS   41472
#define OFF_WS    50176   /* 2048: weights; later H partials (1536) */
#define OFF_BS    52224
#define OFF_RMAX  52352
#define OFF_RSC   52480   /* rsumI -> rsc = rsumI/fr */
#define OFF_CMAX  52608
#define OFF_GCC   52736   /* gcc = gc*csumI */
#define OFF_VL    52864
#define OFF_VR    52992
#define OFF_PART  53120   /* 2048: colmax partials / csump / Dg(384)+Dh(384) */
#define OFF_FR    55168
#define OFF_GC    55296
#define OFF_MG    55424
#define ATTN_SMEM ((55424 + 32)*4)

__global__ __launch_bounds__(1024, 1) void attn_kernel(
    const float* __restrict__ t2, const float* __restrict__ xL,
    const float* __restrict__ xR,
    const float* __restrict__ qw, const float* __restrict__ qb,
    const float* __restrict__ kw_, const float* __restrict__ kb,
    float* __restrict__ outL, float* __restrict__ outR) {
  extern __shared__ float sm[];
  float* Am    = sm;               // t2 stage -> S -> A' = exp(S - M)
  float* Bm    = sm + OFF_BM;      // Q/K (k-major), dead after GEMM1
  float* xls   = sm + OFF_XLS;
  float* xrs   = sm + OFF_XRS;
  float* ws    = sm + OFF_WS;
  float* bs    = sm + OFF_BS;
  float* rmax  = sm + OFF_RMAX;
  float* rsc   = sm + OFF_RSC;
  float* cmax  = sm + OFF_CMAX;
  float* gcc   = sm + OFF_GCC;
  float* Vl    = sm + OFF_VL;
  float* Vr    = sm + OFF_VR;
  float* part  = sm + OFF_PART;
  float* fr    = sm + OFF_FR;
  float* gc    = sm + OFF_GC;
  float* Mg    = sm + OFF_MG;
  int n = blockIdx.x, b = n >> 7, h = n & 127;
  int t = threadIdx.x, warp = t >> 5, lane = t & 31;

  // stage weights/bias + both t2 rows
  for (int i = t; i < 2048; i += 1024) ws[i] = (i < 1024) ? qw[i] : kw_[i-1024];
  if (t < 128) bs[t] = (t < 64) ? qb[t] : kb[t-64];
  for (int i = t; i < 16384; i += 1024) {
    int c = i >> 7, u = i & 127;
    size_t gi = ((c >= 64) ? (size_t)IMG : 0) +
                ((size_t)(b*NC + (c & 63))*NH + h)*NW + u;
    Am[c*ST + u] = t2[gi];
  }
  __syncthreads();

  // 1x1 grouped conv: Bm[k][u]
  for (int i = t; i < 8192; i += 1024) {
    int k = i >> 6, up = (i & 63)*2;
    int cb = (k >> 4) * 16;
    float bzv = bs[k];
    u64 a = f2pk(bzv, bzv);
    #pragma unroll
    for (int ic = 0; ic < 16; ic++) {
      u64 w2 = f2dup(ws[k*16 + ic]);
      u64 xp = *(const u64*)&Am[(cb + ic)*ST + up];
      fma2(a, w2, xp);
    }
    *(u64*)&Bm[k*ST + up] = a;
  }
  __syncthreads();

  // row-mean subtract
  for (int r = warp; r < 128; r += 32) {
    float s = 0.f;
    for (int u = lane; u < 128; u += 32) s += Bm[r*ST + u];
    #pragma unroll
    for (int off = 16; off; off >>= 1) s += __shfl_xor_sync(0xffffffffu, s, off);
    float mean = s * (1.f/128.f);
    for (int u = lane; u < 128; u += 32) Bm[r*ST + u] -= mean;
  }
  __syncthreads();

  // GEMM1: S[u][v] (4u x 4v) + fused row-max + col-max partials
  int g1u0 = warp * 4, g1v0 = lane * 4;
  float cmv[4] = {-1e30f, -1e30f, -1e30f, -1e30f};
  {
    u64 acc2[4][2];
    #pragma unroll
    for (int i = 0; i < 4; i++) { acc2[i][0] = 0ull; acc2[i][1] = 0ull; }
    for (int k = 0; k < 64; k++) {
      float4 qv = *(const float4*)&Bm[k*ST + g1u0];
      ulonglong2 kv = *(const ulonglong2*)&Bm[(64+k)*ST + g1v0];
      u64 q0 = f2dup(qv.x), q1 = f2dup(qv.y), q2 = f2dup(qv.z), q3 = f2dup(qv.w);
      fma2(acc2[0][0], q0, kv.x); fma2(acc2[0][1], q0, kv.y);
      fma2(acc2[1][0], q1, kv.x); fma2(acc2[1][1], q1, kv.y);
      fma2(acc2[2][0], q2, kv.x); fma2(acc2[2][1], q2, kv.y);
      fma2(acc2[3][0], q3, kv.x); fma2(acc2[3][1], q3, kv.y);
    }
    #pragma unroll
    for (int i = 0; i < 4; i++) {
      float2 a = f2up(acc2[i][0]), c2 = f2up(acc2[i][1]);
      *(float4*)&Am[(g1u0+i)*ST + g1v0] = make_float4(a.x,a.y,c2.x,c2.y);
      float rm = fmaxf(fmaxf(a.x, a.y), fmaxf(c2.x, c2.y));
      #pragma unroll
      for (int off = 16; off; off >>= 1) rm = fmaxf(rm, __shfl_xor_sync(0xffffffffu, rm, off));
      if (lane == 0) rmax[g1u0+i] = rm;
      cmv[0] = fmaxf(cmv[0], a.x);  cmv[1] = fmaxf(cmv[1], a.y);
      cmv[2] = fmaxf(cmv[2], c2.x); cmv[3] = fmaxf(cmv[3], c2.y);
    }
    if (warp < 16)
      *(float4*)&part[warp*128 + g1v0] = make_float4(cmv[0],cmv[1],cmv[2],cmv[3]);
  }
  __syncthreads();

  // col-max stage 2 + x staging
  if (warp >= 16) {
    float4 old = *(const float4*)&part[(warp-16)*128 + g1v0];
    old.x = fmaxf(old.x, cmv[0]); old.y = fmaxf(old.y, cmv[1]);
    old.z = fmaxf(old.z, cmv[2]); old.w = fmaxf(old.w, cmv[3]);
    *(float4*)&part[(warp-16)*128 + g1v0] = old;
  }
  for (int i = t; i < 8192; i += 1024) {
    int c = i >> 7, v = i & 127;
    size_t gi = ((size_t)(b*NC + c)*NH + h)*NW + v;
    xls[v*XST + c] = xL[gi];
    xrs[v*XST + c] = xR[gi];
  }
  __syncthreads();

  // cmax reduce + global max
  if (t < 128) {
    float m = -1e30f;
    #pragma unroll
    for (int k2 = 0; k2 < 16; k2++) m = fmaxf(m, part[k2*128 + t]);
    cmax[t] = m;
  } else if (t < 160) {
    int l = t - 128;
    float m = fmaxf(fmaxf(rmax[l], rmax[l+32]), fmaxf(rmax[l+64], rmax[l+96]));
    #pragma unroll
    for (int off = 16; off; off >>= 1) m = fmaxf(m, __shfl_xor_sync(0xffffffffu, m, off));
    if (l == 0) Mg[0] = m;
  }
  __syncthreads();
  if (t < 128) {
    float M = Mg[0];
    fr[t] = __expf(rmax[t] - M);
    gc[t] = __expf(M - cmax[t]);
  }
  __syncthreads();

  // Phase B: Am := A' = exp(S - M) = exp(S - rmax[r]) * fr[r]; row/col sums
  if (warp < 16) {
    float gcv[4];
    #pragma unroll
    for (int k = 0; k < 4; k++) gcv[k] = gc[lane + k*32];
    float csump[4] = {0.f, 0.f, 0.f, 0.f};
    for (int rr = 0; rr < 8; rr++) {
      int r = warp*8 + rr;
      float rm = rmax[r];
      float frv = fr[r];
      float rs = 0.f;
      #pragma unroll
      for (int k = 0; k < 4; k++) {
        int c = lane + k*32;
        float e = __expf(Am[r*ST + c] - rm);
        float ap = e * frv;
        Am[r*ST + c] = ap;
        rs += e;
        csump[k] += ap * gcv[k];
      }
      #pragma unroll
      for (int off = 16; off; off >>= 1) rs += __shfl_xor_sync(0xffffffffu, rs, off);
      if (lane == 0) rsc[r] = 1.f / rs;   // rsumI for now
    }
    #pragma unroll
    for (int k = 0; k < 4; k++) part[warp*128 + k*32 + lane] = csump[k];
  }
  __syncthreads();
  if (t < 128) {
    float s = 0.f;
    #pragma unroll
    for (int w = 0; w < 16; w++) s += part[w*128 + t];
    gcc[t] = gc[t] / s;                      // gc * csumI
    rsc[t] = __fdividef(rsc[t], fr[t]);      // rsumI / fr
  }
  __syncthreads();

  // Banded Grams of A':  Dg[k][i] = sum_v A'[i][v]A'[i+k][v]*gcc[v]  (k=0..2)
  //                      Dh[k][i] = sum_v A'[v][i]A'[v][i+k]*rsc[v]
  if (warp < 16) {                    // G: rows, 8 per warp, full v coverage
    int a0 = warp * 8;
    float acc0[8], acc1[8], acc2g[8];
    #pragma unroll
    for (int i = 0; i < 8; i++) { acc0[i]=0.f; acc1[i]=0.f; acc2g[i]=0.f; }
    #pragma unroll
    for (int vj = 0; vj < 4; vj++) {
      int v = lane + vj*32;
      float w = gcc[v];
      float e[10];
      #pragma unroll
      for (int i = 0; i < 10; i++) e[i] = (a0+i < 128) ? Am[(a0+i)*ST + v] : 0.f;
      #pragma unroll
      for (int i = 0; i < 8; i++) {
        float ew = e[i]*w;
        acc0[i] += ew*e[i];
        acc1[i] += ew*e[i+1];
        acc2g[i] += ew*e[i+2];
      }
    }
    #pragma unroll
    for (int i = 0; i < 8; i++) {
      #pragma unroll
      for (int off = 16; off; off >>= 1) {
        acc0[i]  += __shfl_xor_sync(0xffffffffu, acc0[i],  off);
        acc1[i]  += __shfl_xor_sync(0xffffffffu, acc1[i],  off);
        acc2g[i] += __shfl_xor_sync(0xffffffffu, acc2g[i], off);
      }
      if (lane == 0) {
        part[a0+i]       = acc0[i];
        part[128 + a0+i] = acc1[i];
        part[256 + a0+i] = acc2g[i];
      }
    }
  } else {                            // H: columns, shfl_down neighbors
    int idx = warp - 16, cb = idx & 3, vc = idx >> 2;
    int c = cb*32 + lane;
    float h0 = 0.f, h1 = 0.f, h2 = 0.f;
    for (int v = vc*32; v < vc*32 + 32; v++) {
      float e = Am[v*ST + c];
      float e1 = __shfl_down_sync(0xffffffffu, e, 1);
      float e2 = __shfl_down_sync(0xffffffffu, e, 2);
      if (lane >= 30) e2 = (c+2 < 128) ? Am[v*ST + c + 2] : 0.f;
      if (lane == 31) e1 = (c+1 < 128) ? Am[v*ST + c + 1] : 0.f;
      float ew = e * rsc[v];
      h0 += ew*e; h1 += ew*e1; h2 += ew*e2;
    }
    ws[vc*384 + c]       = h0;
    ws[vc*384 + 128 + c] = h1;
    ws[vc*384 + 256 + c] = h2;
  }
  __syncthreads();

  // Dh reduce + V_left
  if (t < 384) {
    part[384 + t] = ws[t] + ws[384+t] + ws[768+t] + ws[1152+t];
  } else if (t >= 512 && t < 640) {
    int u = t - 512;
    float accL = rsc[u]*part[u];
    if (u+1 < 128) accL += rsc[u+1]*part[128+u];
    if (u+2 < 128) accL += rsc[u+2]*part[256+u];
    if (u >= 1)    accL += rsc[u-1]*part[128+u-1];
    if (u >= 2)    accL += rsc[u-2]*part[256+u-2];
    Vl[u] = tanhf(5.f*accL);
  }
  __syncthreads();
  if (t < 128) {
    int u = t;
    float accR = gcc[u]*part[384+u];
    if (u+1 < 128) accR += gcc[u+1]*part[512+u];
    if (u+2 < 128) accR += gcc[u+2]*part[640+u];
    if (u >= 1)    accR += gcc[u-1]*part[512+u-1];
    if (u >= 2)    accR += gcc[u-2]*part[640+u-2];
    Vr[u] = tanhf(5.f*accR);
  }

  // GEMM2 (g0): xlT[u][c] = rsc[u]*sum_v A'[u][v]*xr[v][c]   (4u x 4c)
  // GEMM3 (g1): xrT[u][c] = gcc[u]*sum_v A'[v][u]*xl[v][c]
  int group = t >> 9;
  int tid = t & 511;
  int c0 = (tid & 15)*4, u0 = (tid >> 4)*4;
  u64 acc2[4][2];
  #pragma unroll
  for (int i = 0; i < 4; i++) { acc2[i][0] = 0ull; acc2[i][1] = 0ull; }

  if (group == 0) {
    for (int v0g = 0; v0g < 128; v0g += 4) {
      ulonglong2 x0 = *(const ulonglong2*)&xrs[(v0g+0)*XST + c0];
      ulonglong2 x1 = *(const ulonglong2*)&xrs[(v0g+1)*XST + c0];
      ulonglong2 x2 = *(const ulonglong2*)&xrs[(v0g+2)*XST + c0];
      ulonglong2 x3 = *(const ulonglong2*)&xrs[(v0g+3)*XST + c0];
      #pragma unroll
      for (int i = 0; i < 4; i++) {
        float4 m = *(const float4*)&Am[(u0+i)*ST + v0g];
        u64 m0 = f2dup(m.x), m1 = f2dup(m.y), m2 = f2dup(m.z), m3 = f2dup(m.w);
        fma2(acc2[i][0], m0, x0.x); fma2(acc2[i][1], m0, x0.y);
        fma2(acc2[i][0], m1, x1.x); fma2(acc2[i][1], m1, x1.y);
        fma2(acc2[i][0], m2, x2.x); fma2(acc2[i][1], m2, x2.y);
        fma2(acc2[i][0], m3, x3.x); fma2(acc2[i][1], m3, x3.y);
      }
    }
  } else {
    for (int v = 0; v < 128; v++) {
      ulonglong2 xp = *(const ulonglong2*)&xls[v*XST + c0];
      float4 b0 = *(const float4*)&Am[v*ST + u0];
      u64 b0d = f2dup(b0.x), b1d = f2dup(b0.y), b2d = f2dup(b0.z), b3d = f2dup(b0.w);
      fma2(acc2[0][0], b0d, xp.x); fma2(acc2[0][1], b0d, xp.y);
      fma2(acc2[1][0], b1d, xp.x); fma2(acc2[1][1], b1d, xp.y);
      fma2(acc2[2][0], b2d, xp.x); fma2(acc2[2][1], b2d, xp.y);
      fma2(acc2[3][0], b3d, xp.x); fma2(acc2[3][1], b3d, xp.y);
    }
  }
  __syncthreads();

  // blend in place
  if (group == 0) {
    #pragma unroll
    for (int i = 0; i < 4; i++) {
      int u = u0 + i;
      float vl = Vl[u];
      float gsc = vl * rsc[u];
      float2 f0 = f2up(acc2[i][0]), f1 = f2up(acc2[i][1]);
      float xt[4] = {f0.x, f0.y, f1.x, f1.y};
      #pragma unroll
      for (int cc = 0; cc < 4; cc++) {
        int x = u*XST + c0 + cc;
        xls[x] = xls[x]*(1.f - vl) + xt[cc]*gsc;
      }
    }
  } else {
    #pragma unroll
    for (int i = 0; i < 4; i++) {
      int u = u0 + i;
      float vr = Vr[u];
      float gsc = vr * gcc[u];
      float2 f0 = f2up(acc2[i][0]), f1 = f2up(acc2[i][1]);
      float xt[4] = {f0.x, f0.y, f1.x, f1.y};
      #pragma unroll
      for (int cc = 0; cc < 4; cc++) {
        int x = u*XST + c0 + cc;
        xrs[x] = xrs[x]*(1.f - vr) + xt[cc]*gsc;
      }
    }
  }
  __syncthreads();

  for (int i = t; i < 8192; i += 1024) {
    int c = i >> 7, u = i & 127;
    size_t gi = ((size_t)(b*NC + c)*NH + h)*NW + u;
    outL[gi] = xls[u*XST + c];
    outR[gi] = xrs[u*XST + c];
  }
}

// ---------------- host ------------------------------------------------------
extern "C" void kernel_launch(void* const* d_in, const int* in_sizes, int n_in,
                              void* d_out, int out_size) {
  const float* xL    = (const float*)d_in[0];
  const float* xR    = (const float*)d_in[1];
  const float* gamma = (const float*)d_in[2];
  const float* beta  = (const float*)d_in[3];
  const float* w1    = (const float*)d_in[4];
  const float* b1    = (const float*)d_in[5];
  const float* w2    = (const float*)d_in[6];
  const float* b2    = (const float*)d_in[7];
  const float* qw    = (const float*)d_in[8];
  const float* qb    = (const float*)d_in[9];
  const float* kw    = (const float*)d_in[10];
  const float* kb    = (const float*)d_in[11];
  float* outL = (float*)d_out;
  float* outR = outL + (size_t)IMG;

  float *t1, *t2;
  cudaGetSymbolAddress((void**)&t1, g_t1);
  cudaGetSymbolAddress((void**)&t2, g_t2);

  cudaFuncSetAttribute(conv3x3_kernel<true>,  cudaFuncAttributeMaxDynamicSharedMemorySize, CONV_SMEM);
  cudaFuncSetAttribute(conv3x3_kernel<false>, cudaFuncAttributeMaxDynamicSharedMemorySize, CONV_SMEM);
  cudaFuncSetAttribute(attn_kernel, cudaFuncAttributeMaxDynamicSharedMemorySize, ATTN_SMEM);

  bn_stats_kernel<<<128, 256>>>(xL, xR, gamma, beta);

  dim3 cgrid(NH/4, NB*NG, 2);
  conv3x3_kernel<true ><<<cgrid, 256, CONV_SMEM>>>(xL, xR, t1, t2, w1, b1);
  conv3x3_kernel<false><<<cgrid, 256, CONV_SMEM>>>(xL, xR, t1, t2, w2, b2);

  attn_kernel<<<NROW, 1024, ATTN_SMEM>>>(t2, xL, xR, qw, qb, kw, kb, outL, outR);
}

// round 9
// speedup vs baseline: 1.1742x; 1.0046x over previous
#include <cuda_runtime.h>
#include <math.h>

#define NB 8
#define NC 64
#define NG 4
#define CG 16
#define NH 128
#define NW 128
#define HW (NH*NW)
#define IMG (NB*NC*HW)
#define NROW (NB*NH)

typedef unsigned long long u64;

__device__ __forceinline__ u64 f2dup(float v) {
  u64 r; asm("mov.b64 %0, {%1, %1};" : "=l"(r) : "f"(v)); return r;
}
__device__ __forceinline__ u64 f2pk(float a, float b) {
  u64 r; asm("mov.b64 %0, {%1, %2};" : "=l"(r) : "f"(a), "f"(b)); return r;
}
__device__ __forceinline__ void fma2(u64& d, u64 a, u64 b) {
  asm("fma.rn.f32x2 %0, %1, %2, %0;" : "+l"(d) : "l"(a), "l"(b));
}
__device__ __forceinline__ float2 f2up(u64 v) {
  float2 f; asm("mov.b64 {%0, %1}, %2;" : "=f"(f.x), "=f"(f.y) : "l"(v)); return f;
}

// ---------------- scratch ----------------------------------------------------
__device__ float g_t1[2*(size_t)IMG];
__device__ float g_t2[2*(size_t)IMG];
__device__ float g_bnA[2][NC];
__device__ float g_bnB[2][NC];
__device__ __align__(16) float g_wt[2][NG*CG*CG*9];   // [layer][g][ic][kh][kw][16oc]

// ---------------- BN statistics ----------------------------------------------
__global__ __launch_bounds__(256) void bn_stats_kernel(
    const float* __restrict__ xl, const float* __restrict__ xr,
    const float* __restrict__ gamma, const float* __restrict__ beta) {
  int c = blockIdx.x & 63;
  int img = blockIdx.x >> 6;
  const float4* x = (const float4*)(img ? xr : xl);
  int t = threadIdx.x;
  float s = 0.f, s2 = 0.f;
  for (int b = 0; b < NB; b++) {
    const float4* p = x + (size_t)(b*NC + c)*(HW/4);
    for (int i = t; i < HW/4; i += 256) {
      float4 v = p[i];
      s  += v.x + v.y + v.z + v.w;
      s2 += v.x*v.x + v.y*v.y + v.z*v.z + v.w*v.w;
    }
  }
  __shared__ float sh[256], sh2[256];
  sh[t] = s; sh2[t] = s2; __syncthreads();
  for (int off = 128; off; off >>= 1) {
    if (t < off) { sh[t] += sh[t+off]; sh2[t] += sh2[t+off]; }
    __syncthreads();
  }
  if (t == 0) {
    const float inv = 1.f / (float)(NB*HW);
    float mean = sh[0] * inv;
    float var  = sh2[0] * inv - mean*mean;
    float a = gamma[c] * rsqrtf(var + 1e-5f);
    g_bnA[img][c] = a;
    g_bnB[img][c] = beta[c] - mean * a;
  }
}

// ---------------- weight transpose: [g][oc][ic][3][3] -> [g][ic*9][16oc] -----
__global__ __launch_bounds__(256) void wtrans_kernel(
    const float* __restrict__ w1, const float* __restrict__ w2) {
  int i = blockIdx.x * 256 + threadIdx.x;      // 2 * 9216
  if (i >= 2*NG*CG*CG*9) return;
  int layer = i >= NG*CG*CG*9;
  int j = layer ? i - NG*CG*CG*9 : i;
  int g = j / (CG*CG*9);
  int r = j - g*(CG*CG*9);
  int oc = r & 15;
  int rest = r >> 4;                            // ic*9 + kh*3 + kw
  const float* src = layer ? w2 : w1;
  g_wt[layer][j] = src[g*CG*CG*9 + oc*CG*9 + rest];
}

// ---------------- grouped 3x3 conv: 8oc x 4w, weights via L1 LDG -------------
#define IN_ST 132
#define CONV_SMEM (CG*6*IN_ST*4)   // 50688 B -> 4 CTAs/SM = 202752 B

template<bool FIRST>
__global__ __launch_bounds__(256, 4) void conv3x3_kernel(
    const float* __restrict__ xL, const float* __restrict__ xR,
    float* __restrict__ t1, float* __restrict__ t2,
    const float* __restrict__ wt, const float* __restrict__ bias) {
  extern __shared__ float sm[];
  float* in_s = sm;                 // [16ic][6r][132]
  int t = threadIdx.x;
  int img = blockIdx.z;
  int b = blockIdx.y >> 2, g = blockIdx.y & 3;
  int h0 = blockIdx.x * 4;
  const float* xorig = img ? xR : xL;
  const float* xin = FIRST ? xorig : (t1 + (size_t)img*IMG);
  float* out = (FIRST ? t1 : t2) + (size_t)img*IMG;

  for (int i = t; i < CG*6*IN_ST; i += 256) {
    int ic  = i / (6*IN_ST);
    int rem = i - ic*(6*IN_ST);
    int r   = rem / IN_ST;
    int wc  = rem - r*IN_ST;
    int hh  = h0 - 1 + r;
    int ww  = wc - 1;
    float v = 0.f;
    if ((unsigned)hh < (unsigned)NH && (unsigned)ww < (unsigned)NW) {
      v = xin[((size_t)(b*NC + g*CG + ic)*NH + hh)*NW + ww];
      if (FIRST) v = g_bnA[img][g*CG+ic]*v + g_bnB[img][g*CG+ic];
    }
    in_s[i] = v;
  }
  __syncthreads();

  int wseg = t & 31, hh2 = (t >> 5) & 3, ocq = t >> 7;
  int w0 = wseg * 4, oc0 = ocq * 8;
  const float* wg = wt + g*(CG*CG*9) + oc0;

  u64 acc2[4][4];
  #pragma unroll
  for (int p = 0; p < 4; p++) {
    u64 bz = f2pk(bias[g*CG+oc0+2*p], bias[g*CG+oc0+2*p+1]);
    #pragma unroll
    for (int j = 0; j < 4; j++) acc2[p][j] = bz;
  }

  for (int ic = 0; ic < CG; ic++) {
    #pragma unroll
    for (int kh = 0; kh < 3; kh++) {
      const float* row = in_s + (ic*6 + hh2 + kh)*IN_ST + w0;
      float4 A  = *(const float4*)row;
      float2 C2 = *(const float2*)(row + 4);
      u64 ind[6];
      ind[0]=f2dup(A.x); ind[1]=f2dup(A.y); ind[2]=f2dup(A.z);
      ind[3]=f2dup(A.w); ind[4]=f2dup(C2.x); ind[5]=f2dup(C2.y);
      const float* wb0 = wg + (ic*3 + kh)*48;   // [kw][16oc]
      #pragma unroll
      for (int kw = 0; kw < 3; kw++) {
        ulonglong2 wA = __ldg((const ulonglong2*)(wb0 + kw*16));
        ulonglong2 wB = __ldg((const ulonglong2*)(wb0 + kw*16 + 4));
        #pragma unroll
        for (int j = 0; j < 4; j++) {
          fma2(acc2[0][j], ind[kw+j], wA.x);
          fma2(acc2[1][j], ind[kw+j], wA.y);
          fma2(acc2[2][j], ind[kw+j], wB.x);
          fma2(acc2[3][j], ind[kw+j], wB.y);
        }
      }
    }
  }

  int hout = h0 + hh2;
  #pragma unroll
  for (int o = 0; o < 8; o++) {
    int ch = g*CG + oc0 + o;
    size_t idx = ((size_t)(b*NC + ch)*NH + hout)*NW + w0;
    float r[4];
    #pragma unroll
    for (int j = 0; j < 4; j++) {
      float2 f = f2up(acc2[o>>1][j]);
      r[j] = (o & 1) ? f.y : f.x;
    }
    if (FIRST) {
      #pragma unroll
      for (int j = 0; j < 4; j++) r[j] = r[j] > 0.f ? r[j] : 0.1f*r[j];
    } else {
      float ra = g_bnA[img][ch], rb = g_bnB[img][ch];
      float4 x0 = *(const float4*)&xorig[idx];
      float xs[4] = {x0.x,x0.y,x0.z,x0.w};
      #pragma unroll
      for (int j = 0; j < 4; j++) r[j] = r[j] + ra*xs[j] + rb;
    }
    *(float4*)&out[idx] = make_float4(r[0],r[1],r[2],r[3]);
  }
}

// ---------------- fused attention (R7, unchanged) -----------------------------
#define ST 128
#define XST 68
#define OFF_BM    16384
#define OFF_XLS   32768
#define OFF_XRS   41472
#define OFF_WS    50176
#define OFF_BS    52224
#define OFF_RMAX  52352
#define OFF_RSC   52480
#define OFF_CMAX  52608
#define OFF_GCC   52736
#define OFF_VL    52864
#define OFF_VR    52992
#define OFF_PART  53120
#define OFF_FR    55168
#define OFF_GC    55296
#define OFF_MG    55424
#define ATTN_SMEM ((55424 + 32)*4)

__global__ __launch_bounds__(1024, 1) void attn_kernel(
    const float* __restrict__ t2, const float* __restrict__ xL,
    const float* __restrict__ xR,
    const float* __restrict__ qw, const float* __restrict__ qb,
    const float* __restrict__ kw_, const float* __restrict__ kb,
    float* __restrict__ outL, float* __restrict__ outR) {
  extern __shared__ float sm[];
  float* Am    = sm;
  float* Bm    = sm + OFF_BM;
  float* xls   = sm + OFF_XLS;
  float* xrs   = sm + OFF_XRS;
  float* ws    = sm + OFF_WS;
  float* bs    = sm + OFF_BS;
  float* rmax  = sm + OFF_RMAX;
  float* rsc   = sm + OFF_RSC;
  float* cmax  = sm + OFF_CMAX;
  float* gcc   = sm + OFF_GCC;
  float* Vl    = sm + OFF_VL;
  float* Vr    = sm + OFF_VR;
  float* part  = sm + OFF_PART;
  float* fr    = sm + OFF_FR;
  float* gc    = sm + OFF_GC;
  float* Mg    = sm + OFF_MG;
  int n = blockIdx.x, b = n >> 7, h = n & 127;
  int t = threadIdx.x, warp = t >> 5, lane = t & 31;

  for (int i = t; i < 2048; i += 1024) ws[i] = (i < 1024) ? qw[i] : kw_[i-1024];
  if (t < 128) bs[t] = (t < 64) ? qb[t] : kb[t-64];
  for (int i = t; i < 16384; i += 1024) {
    int c = i >> 7, u = i & 127;
    size_t gi = ((c >= 64) ? (size_t)IMG : 0) +
                ((size_t)(b*NC + (c & 63))*NH + h)*NW + u;
    Am[c*ST + u] = t2[gi];
  }
  __syncthreads();

  for (int i = t; i < 8192; i += 1024) {
    int k = i >> 6, up = (i & 63)*2;
    int cb = (k >> 4) * 16;
    float bzv = bs[k];
    u64 a = f2pk(bzv, bzv);
    #pragma unroll
    for (int ic = 0; ic < 16; ic++) {
      u64 w2 = f2dup(ws[k*16 + ic]);
      u64 xp = *(const u64*)&Am[(cb + ic)*ST + up];
      fma2(a, w2, xp);
    }
    *(u64*)&Bm[k*ST + up] = a;
  }
  __syncthreads();

  for (int r = warp; r < 128; r += 32) {
    float s = 0.f;
    for (int u = lane; u < 128; u += 32) s += Bm[r*ST + u];
    #pragma unroll
    for (int off = 16; off; off >>= 1) s += __shfl_xor_sync(0xffffffffu, s, off);
    float mean = s * (1.f/128.f);
    for (int u = lane; u < 128; u += 32) Bm[r*ST + u] -= mean;
  }
  __syncthreads();

  int g1u0 = warp * 4, g1v0 = lane * 4;
  float cmv[4] = {-1e30f, -1e30f, -1e30f, -1e30f};
  {
    u64 acc2[4][2];
    #pragma unroll
    for (int i = 0; i < 4; i++) { acc2[i][0] = 0ull; acc2[i][1] = 0ull; }
    for (int k = 0; k < 64; k++) {
      float4 qv = *(const float4*)&Bm[k*ST + g1u0];
      ulonglong2 kv = *(const ulonglong2*)&Bm[(64+k)*ST + g1v0];
      u64 q0 = f2dup(qv.x), q1 = f2dup(qv.y), q2 = f2dup(qv.z), q3 = f2dup(qv.w);
      fma2(acc2[0][0], q0, kv.x); fma2(acc2[0][1], q0, kv.y);
      fma2(acc2[1][0], q1, kv.x); fma2(acc2[1][1], q1, kv.y);
      fma2(acc2[2][0], q2, kv.x); fma2(acc2[2][1], q2, kv.y);
      fma2(acc2[3][0], q3, kv.x); fma2(acc2[3][1], q3, kv.y);
    }
    #pragma unroll
    for (int i = 0; i < 4; i++) {
      float2 a = f2up(acc2[i][0]), c2 = f2up(acc2[i][1]);
      *(float4*)&Am[(g1u0+i)*ST + g1v0] = make_float4(a.x,a.y,c2.x,c2.y);
      float rm = fmaxf(fmaxf(a.x, a.y), fmaxf(c2.x, c2.y));
      #pragma unroll
      for (int off = 16; off; off >>= 1) rm = fmaxf(rm, __shfl_xor_sync(0xffffffffu, rm, off));
      if (lane == 0) rmax[g1u0+i] = rm;
      cmv[0] = fmaxf(cmv[0], a.x);  cmv[1] = fmaxf(cmv[1], a.y);
      cmv[2] = fmaxf(cmv[2], c2.x); cmv[3] = fmaxf(cmv[3], c2.y);
    }
    if (warp < 16)
      *(float4*)&part[warp*128 + g1v0] = make_float4(cmv[0],cmv[1],cmv[2],cmv[3]);
  }
  __syncthreads();

  if (warp >= 16) {
    float4 old = *(const float4*)&part[(warp-16)*128 + g1v0];
    old.x = fmaxf(old.x, cmv[0]); old.y = fmaxf(old.y, cmv[1]);
    old.z = fmaxf(old.z, cmv[2]); old.w = fmaxf(old.w, cmv[3]);
    *(float4*)&part[(warp-16)*128 + g1v0] = old;
  }
  for (int i = t; i < 8192; i += 1024) {
    int c = i >> 7, v = i & 127;
    size_t gi = ((size_t)(b*NC + c)*NH + h)*NW + v;
    xls[v*XST + c] = xL[gi];
    xrs[v*XST + c] = xR[gi];
  }
  __syncthreads();

  if (t < 128) {
    float m = -1e30f;
    #pragma unroll
    for (int k2 = 0; k2 < 16; k2++) m = fmaxf(m, part[k2*128 + t]);
    cmax[t] = m;
  } else if (t < 160) {
    int l = t - 128;
    float m = fmaxf(fmaxf(rmax[l], rmax[l+32]), fmaxf(rmax[l+64], rmax[l+96]));
    #pragma unroll
    for (int off = 16; off; off >>= 1) m = fmaxf(m, __shfl_xor_sync(0xffffffffu, m, off));
    if (l == 0) Mg[0] = m;
  }
  __syncthreads();
  if (t < 128) {
    float M = Mg[0];
    fr[t] = __expf(rmax[t] - M);
    gc[t] = __expf(M - cmax[t]);
  }
  __syncthreads();

  if (warp < 16) {
    float gcv[4];
    #pragma unroll
    for (int k = 0; k < 4; k++) gcv[k] = gc[lane + k*32];
    float csump[4] = {0.f, 0.f, 0.f, 0.f};
    for (int rr = 0; rr < 8; rr++) {
      int r = warp*8 + rr;
      float rm = rmax[r];
      float frv = fr[r];
      float rs = 0.f;
      #pragma unroll
      for (int k = 0; k < 4; k++) {
        int c = lane + k*32;
        float e = __expf(Am[r*ST + c] - rm);
        float ap = e * frv;
        Am[r*ST + c] = ap;
        rs += e;
        csump[k] += ap * gcv[k];
      }
      #pragma unroll
      for (int off = 16; off; off >>= 1) rs += __shfl_xor_sync(0xffffffffu, rs, off);
      if (lane == 0) rsc[r] = 1.f / rs;
    }
    #pragma unroll
    for (int k = 0; k < 4; k++) part[warp*128 + k*32 + lane] = csump[k];
  }
  __syncthreads();
  if (t < 128) {
    float s = 0.f;
    #pragma unroll
    for (int w = 0; w < 16; w++) s += part[w*128 + t];
    gcc[t] = gc[t] / s;
    rsc[t] = __fdividef(rsc[t], fr[t]);
  }
  __syncthreads();

  if (warp < 16) {
    int a0 = warp * 8;
    float acc0[8], acc1[8], acc2g[8];
    #pragma unroll
    for (int i = 0; i < 8; i++) { acc0[i]=0.f; acc1[i]=0.f; acc2g[i]=0.f; }
    #pragma unroll
    for (int vj = 0; vj < 4; vj++) {
      int v = lane + vj*32;
      float w = gcc[v];
      float e[10];
      #pragma unroll
      for (int i = 0; i < 10; i++) e[i] = (a0+i < 128) ? Am[(a0+i)*ST + v] : 0.f;
      #pragma unroll
      for (int i = 0; i < 8; i++) {
        float ew = e[i]*w;
        acc0[i] += ew*e[i];
        acc1[i] += ew*e[i+1];
        acc2g[i] += ew*e[i+2];
      }
    }
    #pragma unroll
    for (int i = 0; i < 8; i++) {
      #pragma unroll
      for (int off = 16; off; off >>= 1) {
        acc0[i]  += __shfl_xor_sync(0xffffffffu, acc0[i],  off);
        acc1[i]  += __shfl_xor_sync(0xffffffffu, acc1[i],  off);
        acc2g[i] += __shfl_xor_sync(0xffffffffu, acc2g[i], off);
      }
      if (lane == 0) {
        part[a0+i]       = acc0[i];
        part[128 + a0+i] = acc1[i];
        part[256 + a0+i] = acc2g[i];
      }
    }
  } else {
    int idx = warp - 16, cb = idx & 3, vc = idx >> 2;
    int c = cb*32 + lane;
    float h0 = 0.f, h1 = 0.f, h2 = 0.f;
    for (int v = vc*32; v < vc*32 + 32; v++) {
      float e = Am[v*ST + c];
      float e1 = __shfl_down_sync(0xffffffffu, e, 1);
      float e2 = __shfl_down_sync(0xffffffffu, e, 2);
      if (lane >= 30) e2 = (c+2 < 128) ? Am[v*ST + c + 2] : 0.f;
      if (lane == 31) e1 = (c+1 < 128) ? Am[v*ST + c + 1] : 0.f;
      float ew = e * rsc[v];
      h0 += ew*e; h1 += ew*e1; h2 += ew*e2;
    }
    ws[vc*384 + c]       = h0;
    ws[vc*384 + 128 + c] = h1;
    ws[vc*384 + 256 + c] = h2;
  }
  __syncthreads();

  if (t < 384) {
    part[384 + t] = ws[t] + ws[384+t] + ws[768+t] + ws[1152+t];
  } else if (t >= 512 && t < 640) {
    int u = t - 512;
    float accL = rsc[u]*part[u];
    if (u+1 < 128) accL += rsc[u+1]*part[128+u];
    if (u+2 < 128) accL += rsc[u+2]*part[256+u];
    if (u >= 1)    accL += rsc[u-1]*part[128+u-1];
    if (u >= 2)    accL += rsc[u-2]*part[256+u-2];
    Vl[u] = tanhf(5.f*accL);
  }
  __syncthreads();
  if (t < 128) {
    int u = t;
    float accR = gcc[u]*part[384+u];
    if (u+1 < 128) accR += gcc[u+1]*part[512+u];
    if (u+2 < 128) accR += gcc[u+2]*part[640+u];
    if (u >= 1)    accR += gcc[u-1]*part[512+u-1];
    if (u >= 2)    accR += gcc[u-2]*part[640+u-2];
    Vr[u] = tanhf(5.f*accR);
  }

  int group = t >> 9;
  int tid = t & 511;
  int c0 = (tid & 15)*4, u0 = (tid >> 4)*4;
  u64 acc2[4][2];
  #pragma unroll
  for (int i = 0; i < 4; i++) { acc2[i][0] = 0ull; acc2[i][1] = 0ull; }

  if (group == 0) {
    for (int v0g = 0; v0g < 128; v0g += 4) {
      ulonglong2 x0 = *(const ulonglong2*)&xrs[(v0g+0)*XST + c0];
      ulonglong2 x1 = *(const ulonglong2*)&xrs[(v0g+1)*XST + c0];
      ulonglong2 x2 = *(const ulonglong2*)&xrs[(v0g+2)*XST + c0];
      ulonglong2 x3 = *(const ulonglong2*)&xrs[(v0g+3)*XST + c0];
      #pragma unroll
      for (int i = 0; i < 4; i++) {
        float4 m = *(const float4*)&Am[(u0+i)*ST + v0g];
        u64 m0 = f2dup(m.x), m1 = f2dup(m.y), m2 = f2dup(m.z), m3 = f2dup(m.w);
        fma2(acc2[i][0], m0, x0.x); fma2(acc2[i][1], m0, x0.y);
        fma2(acc2[i][0], m1, x1.x); fma2(acc2[i][1], m1, x1.y);
        fma2(acc2[i][0], m2, x2.x); fma2(acc2[i][1], m2, x2.y);
        fma2(acc2[i][0], m3, x3.x); fma2(acc2[i][1], m3, x3.y);
      }
    }
  } else {
    for (int v = 0; v < 128; v++) {
      ulonglong2 xp = *(const ulonglong2*)&xls[v*XST + c0];
      float4 b0 = *(const float4*)&Am[v*ST + u0];
      u64 b0d = f2dup(b0.x), b1d = f2dup(b0.y), b2d = f2dup(b0.z), b3d = f2dup(b0.w);
      fma2(acc2[0][0], b0d, xp.x); fma2(acc2[0][1], b0d, xp.y);
      fma2(acc2[1][0], b1d, xp.x); fma2(acc2[1][1], b1d, xp.y);
      fma2(acc2[2][0], b2d, xp.x); fma2(acc2[2][1], b2d, xp.y);
      fma2(acc2[3][0], b3d, xp.x); fma2(acc2[3][1], b3d, xp.y);
    }
  }
  __syncthreads();

  if (group == 0) {
    #pragma unroll
    for (int i = 0; i < 4; i++) {
      int u = u0 + i;
      float vl = Vl[u];
      float gsc = vl * rsc[u];
      float2 f0 = f2up(acc2[i][0]), f1 = f2up(acc2[i][1]);
      float xt[4] = {f0.x, f0.y, f1.x, f1.y};
      #pragma unroll
      for (int cc = 0; cc < 4; cc++) {
        int x = u*XST + c0 + cc;
        xls[x] = xls[x]*(1.f - vl) + xt[cc]*gsc;
      }
    }
  } else {
    #pragma unroll
    for (int i = 0; i < 4; i++) {
      int u = u0 + i;
      float vr = Vr[u];
      float gsc = vr * gcc[u];
      float2 f0 = f2up(acc2[i][0]), f1 = f2up(acc2[i][1]);
      float xt[4] = {f0.x, f0.y, f1.x, f1.y};
      #pragma unroll
      for (int cc = 0; cc < 4; cc++) {
        int x = u*XST + c0 + cc;
        xrs[x] = xrs[x]*(1.f - vr) + xt[cc]*gsc;
      }
    }
  }
  __syncthreads();

  for (int i = t; i < 8192; i += 1024) {
    int c = i >> 7, u = i & 127;
    size_t gi = ((size_t)(b*NC + c)*NH + h)*NW + u;
    outL[gi] = xls[u*XST + c];
    outR[gi] = xrs[u*XST + c];
  }
}

// ---------------- host ------------------------------------------------------
extern "C" void kernel_launch(void* const* d_in, const int* in_sizes, int n_in,
                              void* d_out, int out_size) {
  const float* xL    = (const float*)d_in[0];
  const float* xR    = (const float*)d_in[1];
  const float* gamma = (const float*)d_in[2];
  const float* beta  = (const float*)d_in[3];
  const float* w1    = (const float*)d_in[4];
  const float* b1    = (const float*)d_in[5];
  const float* w2    = (const float*)d_in[6];
  const float* b2    = (const float*)d_in[7];
  const float* qw    = (const float*)d_in[8];
  const float* qb    = (const float*)d_in[9];
  const float* kw    = (const float*)d_in[10];
  const float* kb    = (const float*)d_in[11];
  float* outL = (float*)d_out;
  float* outR = outL + (size_t)IMG;

  float *t1, *t2, *wt;
  cudaGetSymbolAddress((void**)&t1, g_t1);
  cudaGetSymbolAddress((void**)&t2, g_t2);
  cudaGetSymbolAddress((void**)&wt, g_wt);

  cudaFuncSetAttribute(conv3x3_kernel<true>,  cudaFuncAttributeMaxDynamicSharedMemorySize, CONV_SMEM);
  cudaFuncSetAttribute(conv3x3_kernel<false>, cudaFuncAttributeMaxDynamicSharedMemorySize, CONV_SMEM);
  cudaFuncSetAttribute(attn_kernel, cudaFuncAttributeMaxDynamicSharedMemorySize, ATTN_SMEM);

  bn_stats_kernel<<<128, 256>>>(xL, xR, gamma, beta);
  wtrans_kernel<<<(2*NG*CG*CG*9 + 255)/256, 256>>>(w1, w2);

  dim3 cgrid(NH/4, NB*NG, 2);
  conv3x3_kernel<true ><<<cgrid, 256, CONV_SMEM>>>(xL, xR, t1, t2, wt, b1);
  conv3x3_kernel<false><<<cgrid, 256, CONV_SMEM>>>(xL, xR, t1, t2, wt + NG*CG*CG*9, b2);

  attn_kernel<<<NROW, 1024, ATTN_SMEM>>>(t2, xL, xR, qw, qb, kw, kb, outL, outR);
}